// round 1
// baseline (speedup 1.0000x reference)
#include <cuda_runtime.h>
#include <cuda_bf16.h>
#include <math.h>

// ---------------------------------------------------------------------------
// Problem constants
// ---------------------------------------------------------------------------
#define NB   16
#define CIN  1024
#define CMID 256
#define C8   32
#define HH   48
#define WW   48
#define HW   (HH*WW)          // 2304
#define NTOT (NB*HW)          // 36864
#define OCH  512
#define NCLS 21
#define NEG_INF (__int_as_float(0xff800000))

// ---------------------------------------------------------------------------
// Static scratch (no cudaMalloc allowed)
// ---------------------------------------------------------------------------
__device__ float g_t0[NB*CMID*HW];     // conv temp (256 ch)
__device__ float g_cc[NB*CMID*HW];
__device__ float g_my[NB*CMID*HW];
__device__ float g_t1[NB*CMID*HW];     // attention ping-pong
__device__ float g_q [NB*C8*HW];
__device__ float g_k [NB*C8*HW];
__device__ float g_v [NB*CMID*HW];
__device__ float g_h [NB*OCH*HW];      // 512-ch conv temp
__device__ float g_stats[2*OCH];       // per-channel scale/shift
__device__ float g_S[256];             // 16x16 gram
__device__ float g_Wm[256];            // 16x16 attention weights

// ---------------------------------------------------------------------------
// Tiled implicit-GEMM: out[b,m,hw] = sum_k W[m,k] * im2col(in)[k, b*HW+hw]
// Handles 3x3 (K = Cin*9, pad=1) and 1x1 (K = Cin). Input may be a concat of
// up to 3 channel segments (p0:c0, p1:c1, p2:c2). Optional bias.
// Tile: 128(M) x 128(N) x 16(K); 256 threads; 8x8 per thread (interleaved).
// ---------------------------------------------------------------------------
__global__ __launch_bounds__(256) void gemm_conv_kernel(
    const float* __restrict__ Wt,
    const float* __restrict__ p0, const float* __restrict__ p1, const float* __restrict__ p2,
    int c0, int c1, int c2,
    int M, int Cin, int is3x3,
    const float* __restrict__ bias,
    float* __restrict__ out)
{
    __shared__ float As[16][128];
    __shared__ float Bs[16][128];

    const int tid = threadIdx.x;
    const int tx = tid & 15, ty = tid >> 4;
    const int m0 = blockIdx.y * 128;
    const int n0 = blockIdx.x * 128;
    const int K  = is3x3 ? Cin * 9 : Cin;

    float acc[8][8];
#pragma unroll
    for (int i = 0; i < 8; i++)
#pragma unroll
        for (int j = 0; j < 8; j++) acc[i][j] = 0.f;

    // B-load thread mapping: nl in [0,128), kbB in {0,8}
    const int nl  = tid & 127;
    const int nglob = n0 + nl;
    const int bb  = nglob / HW;
    const int hw  = nglob - bb * HW;
    const int yy0 = hw / WW;
    const int xx0 = hw - yy0 * WW;
    const int kbB = (tid >> 7) * 8;
    // A-load thread mapping: ml in [0,128), kbA in {0,8}
    const int ml  = tid >> 1;
    const int kbA = (tid & 1) * 8;

    for (int k0 = 0; k0 < K; k0 += 16) {
        // ---- load A tile (weights) ----
        {
            int m = m0 + ml;
            const float* wp = Wt + (size_t)m * K + (k0 + kbA);
#pragma unroll
            for (int i = 0; i < 8; i++)
                As[kbA + i][ml] = (m < M) ? wp[i] : 0.f;
        }
        // ---- load B tile (im2col gather) ----
        {
#pragma unroll
            for (int i = 0; i < 8; i++) {
                int kg = k0 + kbB + i;
                int ci, yq, xq;
                if (is3x3) {
                    ci = kg / 9;
                    int t9 = kg - ci * 9;
                    int ky = t9 / 3;
                    yq = yy0 + ky - 1;
                    xq = xx0 + (t9 - ky * 3) - 1;
                } else { ci = kg; yq = yy0; xq = xx0; }
                float val = 0.f;
                if (yq >= 0 && yq < HH && xq >= 0 && xq < WW) {
                    const float* src; int cl, cn;
                    if (ci < c0)           { src = p0; cl = ci;            cn = c0; }
                    else if (ci < c0 + c1) { src = p1; cl = ci - c0;       cn = c1; }
                    else                   { src = p2; cl = ci - c0 - c1;  cn = c2; }
                    val = src[((size_t)(bb * cn + cl) * HH + yq) * WW + xq];
                }
                Bs[kbB + i][nl] = val;
            }
        }
        __syncthreads();

#pragma unroll
        for (int kk = 0; kk < 16; kk++) {
            float a[8], bq[8];
#pragma unroll
            for (int i = 0; i < 8; i++) a[i]  = As[kk][ty + 16 * i];
#pragma unroll
            for (int j = 0; j < 8; j++) bq[j] = Bs[kk][tx + 16 * j];
#pragma unroll
            for (int i = 0; i < 8; i++)
#pragma unroll
                for (int j = 0; j < 8; j++)
                    acc[i][j] = fmaf(a[i], bq[j], acc[i][j]);
        }
        __syncthreads();
    }

    // ---- store ----
#pragma unroll
    for (int i = 0; i < 8; i++) {
        int m = m0 + ty + 16 * i;
        if (m >= M) continue;
        float bval = bias ? bias[m] : 0.f;
#pragma unroll
        for (int j = 0; j < 8; j++) {
            int n = n0 + tx + 16 * j;
            int b = n / HW;
            int hw2 = n - b * HW;
            out[((size_t)(b * M + m)) * HW + hw2] = acc[i][j] + bval;
        }
    }
}

// ---------------------------------------------------------------------------
// BN stats: per-channel mean/var over (B, H, W) -> folded scale/shift
// One block (256 threads) per channel.
// ---------------------------------------------------------------------------
__global__ void bn_stats_kernel(const float* __restrict__ x,
                                const float* __restrict__ g,
                                const float* __restrict__ bta,
                                float* __restrict__ stats, int C)
{
    int c = blockIdx.x;
    int tid = threadIdx.x;
    float s = 0.f, sq = 0.f;
    for (int i = tid; i < NB * HW; i += 256) {
        int bb = i / HW;
        int hw = i - bb * HW;
        float v = x[((size_t)(bb * C + c)) * HW + hw];
        s += v; sq += v * v;
    }
    __shared__ float sh1[256], sh2[256];
    sh1[tid] = s; sh2[tid] = sq;
    __syncthreads();
    for (int st = 128; st; st >>= 1) {
        if (tid < st) { sh1[tid] += sh1[tid + st]; sh2[tid] += sh2[tid + st]; }
        __syncthreads();
    }
    if (tid == 0) {
        float n   = (float)(NB * HW);
        float m   = sh1[0] / n;
        float var = sh2[0] / n - m * m;
        float sc  = g[c] * rsqrtf(var + 1e-5f);
        stats[2 * c]     = sc;
        stats[2 * c + 1] = bta[c] - m * sc;
    }
}

__global__ void bn_apply_kernel(const float* __restrict__ x,
                                const float* __restrict__ stats,
                                float* __restrict__ y, int C, int total)
{
    int i = blockIdx.x * 256 + threadIdx.x;
    if (i < total) {
        int c = (i / HW) % C;
        y[i] = fmaxf(fmaf(x[i], stats[2 * c], stats[2 * c + 1]), 0.f);
    }
}

// ---------------------------------------------------------------------------
// Criss-cross attention core. One block per (b, h, w); 256 threads.
// out = gamma * (oH + oW) + xin
// ---------------------------------------------------------------------------
__global__ void cc_core_kernel(const float* __restrict__ q,
                               const float* __restrict__ kk_,
                               const float* __restrict__ v,
                               const float* __restrict__ xin,
                               const float* __restrict__ gamma,
                               float* __restrict__ out)
{
    int w = blockIdx.x, h = blockIdx.y, b = blockIdx.z;
    int tid = threadIdx.x;
    __shared__ float qs[32];
    __shared__ float lg[128];
    __shared__ float red[128];

    if (tid < 32) qs[tid] = q[((b * C8 + tid) * HH + h) * WW + w];
    __syncthreads();

    if (tid < 128) {
        float val = NEG_INF;
        if (tid < 48) {
            int g = tid;
            if (g != h) {
                float s = 0.f;
#pragma unroll
                for (int c = 0; c < 32; c++)
                    s += qs[c] * kk_[((b * C8 + c) * HH + g) * WW + w];
                val = s;
            }
        } else if (tid < 96) {
            int v2 = tid - 48;
            float s = 0.f;
#pragma unroll
            for (int c = 0; c < 32; c++)
                s += qs[c] * kk_[((b * C8 + c) * HH + h) * WW + v2];
            val = s;
        }
        lg[tid]  = val;
        red[tid] = val;
    } else if (tid < 256) {
        // nothing
    }
    __syncthreads();
    // max reduce over 128
    for (int st = 64; st; st >>= 1) {
        if (tid < st) red[tid] = fmaxf(red[tid], red[tid + st]);
        __syncthreads();
    }
    float mx = red[0];
    __syncthreads();
    if (tid < 128) {
        float e = expf(lg[tid] - mx);  // -inf -> 0
        lg[tid]  = e;
        red[tid] = e;
    }
    __syncthreads();
    for (int st = 64; st; st >>= 1) {
        if (tid < st) red[tid] += red[tid + st];
        __syncthreads();
    }
    float inv = 1.f / red[0];

    // phase 3: one output channel per thread
    int c = tid;
    float o = 0.f;
#pragma unroll 4
    for (int g = 0; g < 48; g++)
        o += lg[g] * v[((b * CMID + c) * HH + g) * WW + w];
#pragma unroll 4
    for (int v2 = 0; v2 < 48; v2++)
        o += lg[48 + v2] * v[((b * CMID + c) * HH + h) * WW + v2];
    o *= inv;
    size_t oi = ((size_t)(b * CMID + c) * HH + h) * WW + w;
    out[oi] = gamma[0] * o + xin[oi];
}

// ---------------------------------------------------------------------------
// "my" (grid) attention: gram S[b1,b2] = q[b1] . k[b2]  (len 73728)
// ---------------------------------------------------------------------------
__global__ void gram_kernel(const float* __restrict__ q,
                            const float* __restrict__ k,
                            float* __restrict__ S)
{
    int b1 = blockIdx.x >> 4, b2 = blockIdx.x & 15;
    const float* qp = q + (size_t)b1 * (C8 * HW);
    const float* kp = k + (size_t)b2 * (C8 * HW);
    int tid = threadIdx.x;
    float s = 0.f;
    for (int i = tid; i < C8 * HW; i += 256) s += qp[i] * kp[i];
    __shared__ float sh[256];
    sh[tid] = s;
    __syncthreads();
    for (int st = 128; st; st >>= 1) {
        if (tid < st) sh[tid] += sh[tid + st];
        __syncthreads();
    }
    if (tid == 0) S[blockIdx.x] = sh[0];
}

// 16 threads: per-batch masked 8-way softmax -> dense 16x16 weight matrix
__global__ void myw_kernel(const float* __restrict__ S, float* __restrict__ Wm)
{
    int b1 = threadIdx.x;
    if (b1 < 16) {
        int gh = b1 >> 2, gw = b1 & 3;
        float l[8];
        for (int j = 0; j < 4; j++) {
            int b2 = j * 4 + gw;
            l[j] = (j == gh) ? NEG_INF : S[b1 * 16 + b2];
        }
        for (int j = 0; j < 4; j++) l[4 + j] = S[b1 * 16 + gh * 4 + j];
        float mx = NEG_INF;
        for (int j = 0; j < 8; j++) mx = fmaxf(mx, l[j]);
        float sm = 0.f;
        for (int j = 0; j < 8; j++) { l[j] = expf(l[j] - mx); sm += l[j]; }
        float inv = 1.f / sm;
        float w[16];
        for (int i = 0; i < 16; i++) w[i] = 0.f;
        for (int j = 0; j < 4; j++) w[j * 4 + gw] += l[j] * inv;       // column mates
        for (int j = 0; j < 4; j++) w[gh * 4 + j] += l[4 + j] * inv;   // row mates
        for (int i = 0; i < 16; i++) Wm[b1 * 16 + i] = w[i];
    }
}

// out[b1, n] = gamma * sum_b2 W[b1,b2] * v[b2, n] + xin[b1, n]
__global__ void my_combine_kernel(const float* __restrict__ v,
                                  const float* __restrict__ Wm,
                                  const float* __restrict__ xin,
                                  const float* __restrict__ gamma,
                                  float* __restrict__ out)
{
    __shared__ float ws[256];
    if (threadIdx.x < 256) ws[threadIdx.x] = Wm[threadIdx.x];
    __syncthreads();
    const int PB = CMID * HW;  // 589824 per batch
    int n = blockIdx.x * 256 + threadIdx.x;
    if (n < PB) {
        float vv[16];
#pragma unroll
        for (int b = 0; b < 16; b++) vv[b] = v[(size_t)b * PB + n];
        float gm = gamma[0];
#pragma unroll
        for (int b1 = 0; b1 < 16; b1++) {
            float o = 0.f;
#pragma unroll
            for (int b2 = 0; b2 < 16; b2++) o += ws[b1 * 16 + b2] * vv[b2];
            out[(size_t)b1 * PB + n] = gm * o + xin[(size_t)b1 * PB + n];
        }
    }
}

// ---------------------------------------------------------------------------
// Host orchestration
// ---------------------------------------------------------------------------
extern "C" void kernel_launch(void* const* d_in, const int* in_sizes, int n_in,
                              void* d_out, int out_size)
{
    const float* x      = (const float*)d_in[0];
    const float* w_a    = (const float*)d_in[1];
    const float* g_a    = (const float*)d_in[2];
    const float* b_a    = (const float*)d_in[3];
    const float* ccq_w  = (const float*)d_in[4];
    const float* ccq_b  = (const float*)d_in[5];
    const float* cck_w  = (const float*)d_in[6];
    const float* cck_b  = (const float*)d_in[7];
    const float* ccv_w  = (const float*)d_in[8];
    const float* ccv_b  = (const float*)d_in[9];
    const float* cc_gm  = (const float*)d_in[10];
    const float* w_b    = (const float*)d_in[11];
    const float* g_b    = (const float*)d_in[12];
    const float* b_b    = (const float*)d_in[13];
    const float* w_m1   = (const float*)d_in[14];
    const float* g_m1   = (const float*)d_in[15];
    const float* b_m1   = (const float*)d_in[16];
    const float* myq_w  = (const float*)d_in[17];
    const float* myq_b  = (const float*)d_in[18];
    const float* myk_w  = (const float*)d_in[19];
    const float* myk_b  = (const float*)d_in[20];
    const float* myv_w  = (const float*)d_in[21];
    const float* myv_b  = (const float*)d_in[22];
    const float* my_gm  = (const float*)d_in[23];
    const float* w_m2   = (const float*)d_in[24];
    const float* g_m2   = (const float*)d_in[25];
    const float* b_m2   = (const float*)d_in[26];
    const float* w_c    = (const float*)d_in[27];
    const float* g_c    = (const float*)d_in[28];
    const float* b_c    = (const float*)d_in[29];
    const float* w_cls  = (const float*)d_in[30];
    const float* b_cls  = (const float*)d_in[31];

    float *pt0, *pcc, *pmy, *pt1, *pq, *pk, *pv, *ph, *pst, *pS, *pWm;
    cudaGetSymbolAddress((void**)&pt0, g_t0);
    cudaGetSymbolAddress((void**)&pcc, g_cc);
    cudaGetSymbolAddress((void**)&pmy, g_my);
    cudaGetSymbolAddress((void**)&pt1, g_t1);
    cudaGetSymbolAddress((void**)&pq,  g_q);
    cudaGetSymbolAddress((void**)&pk,  g_k);
    cudaGetSymbolAddress((void**)&pv,  g_v);
    cudaGetSymbolAddress((void**)&ph,  g_h);
    cudaGetSymbolAddress((void**)&pst, g_stats);
    cudaGetSymbolAddress((void**)&pS,  g_S);
    cudaGetSymbolAddress((void**)&pWm, g_Wm);

    const dim3 blk(256);
    const int NT = NTOT / 128;  // 288 N-tiles

    // ---- conv_a: x -> t0 (256 ch), BN -> cc ----
    gemm_conv_kernel<<<dim3(NT, 2), blk>>>(w_a, x, x, x, CIN, 0, 0, CMID, CIN, 1, nullptr, pt0);
    bn_stats_kernel<<<CMID, blk>>>(pt0, g_a, b_a, pst, CMID);
    bn_apply_kernel<<<(NB*CMID*HW + 255)/256, blk>>>(pt0, pst, pcc, CMID, NB*CMID*HW);

    // ---- conv_m1: x -> t0, BN -> my ----
    gemm_conv_kernel<<<dim3(NT, 2), blk>>>(w_m1, x, x, x, CIN, 0, 0, CMID, CIN, 1, nullptr, pt0);
    bn_stats_kernel<<<CMID, blk>>>(pt0, g_m1, b_m1, pst, CMID);
    bn_apply_kernel<<<(NB*CMID*HW + 255)/256, blk>>>(pt0, pst, pmy, CMID, NB*CMID*HW);

    // ---- cc attention x2 (ping-pong cc <-> t1) ----
    {
        float* ca = pcc; float* cb = pt1;
        for (int it = 0; it < 2; it++) {
            gemm_conv_kernel<<<dim3(NT, 1), blk>>>(ccq_w, ca, ca, ca, CMID, 0, 0, C8,   CMID, 0, ccq_b, pq);
            gemm_conv_kernel<<<dim3(NT, 1), blk>>>(cck_w, ca, ca, ca, CMID, 0, 0, C8,   CMID, 0, cck_b, pk);
            gemm_conv_kernel<<<dim3(NT, 2), blk>>>(ccv_w, ca, ca, ca, CMID, 0, 0, CMID, CMID, 0, ccv_b, pv);
            cc_core_kernel<<<dim3(WW, HH, NB), blk>>>(pq, pk, pv, ca, cc_gm, cb);
            float* tmp = ca; ca = cb; cb = tmp;
        }
        // result back in pcc (even number of swaps)
    }

    // ---- my attention x2 (ping-pong my <-> t1) ----
    {
        float* ma = pmy; float* mb = pt1;
        for (int it = 0; it < 2; it++) {
            gemm_conv_kernel<<<dim3(NT, 1), blk>>>(myq_w, ma, ma, ma, CMID, 0, 0, C8,   CMID, 0, myq_b, pq);
            gemm_conv_kernel<<<dim3(NT, 1), blk>>>(myk_w, ma, ma, ma, CMID, 0, 0, C8,   CMID, 0, myk_b, pk);
            gemm_conv_kernel<<<dim3(NT, 2), blk>>>(myv_w, ma, ma, ma, CMID, 0, 0, CMID, CMID, 0, myv_b, pv);
            gram_kernel<<<256, blk>>>(pq, pk, pS);
            myw_kernel<<<1, 32>>>(pS, pWm);
            my_combine_kernel<<<(CMID*HW + 255)/256, blk>>>(pv, pWm, ma, my_gm, mb);
            float* tmp = ma; ma = mb; mb = tmp;
        }
    }

    // ---- conv_b: cc -> t0, BN -> cc ----
    gemm_conv_kernel<<<dim3(NT, 2), blk>>>(w_b, pcc, pcc, pcc, CMID, 0, 0, CMID, CMID, 1, nullptr, pt0);
    bn_stats_kernel<<<CMID, blk>>>(pt0, g_b, b_b, pst, CMID);
    bn_apply_kernel<<<(NB*CMID*HW + 255)/256, blk>>>(pt0, pst, pcc, CMID, NB*CMID*HW);

    // ---- conv_m2: my -> t0, BN -> my ----
    gemm_conv_kernel<<<dim3(NT, 2), blk>>>(w_m2, pmy, pmy, pmy, CMID, 0, 0, CMID, CMID, 1, nullptr, pt0);
    bn_stats_kernel<<<CMID, blk>>>(pt0, g_m2, b_m2, pst, CMID);
    bn_apply_kernel<<<(NB*CMID*HW + 255)/256, blk>>>(pt0, pst, pmy, CMID, NB*CMID*HW);

    // ---- conv_c: concat(x, cc, my) 1536 ch -> h (512 ch), BN in-place ----
    gemm_conv_kernel<<<dim3(NT, 4), blk>>>(w_c, x, pcc, pmy, CIN, CMID, CMID,
                                           OCH, CIN + 2*CMID, 1, nullptr, ph);
    bn_stats_kernel<<<OCH, blk>>>(ph, g_c, b_c, pst, OCH);
    bn_apply_kernel<<<(NB*OCH*HW + 255)/256, blk>>>(ph, pst, ph, OCH, NB*OCH*HW);

    // ---- classifier 1x1: h -> out (21 ch) ----
    gemm_conv_kernel<<<dim3(NT, 1), blk>>>(w_cls, ph, ph, ph, OCH, 0, 0,
                                           NCLS, OCH, 0, b_cls, (float*)d_out);
}

// round 2
// speedup vs baseline: 1.0021x; 1.0021x over previous
#include <cuda_runtime.h>
#include <cuda_bf16.h>
#include <math.h>

// ---------------------------------------------------------------------------
// Problem constants
// ---------------------------------------------------------------------------
#define NB   16
#define CIN  1024
#define CMID 256
#define C8   32
#define HH   48
#define WW   48
#define HW   (HH*WW)          // 2304
#define NTOT (NB*HW)          // 36864
#define OCH  512
#define NCLS 21
#define NEG_INF (__int_as_float(0xff800000))

// ---------------------------------------------------------------------------
// Static scratch (no cudaMalloc allowed)
// ---------------------------------------------------------------------------
__device__ float g_t0[NB*CMID*HW];     // conv temp (256 ch)
__device__ float g_cc[NB*CMID*HW];
__device__ float g_my[NB*CMID*HW];
__device__ float g_t1[NB*CMID*HW];     // attention ping-pong
__device__ float g_q [NB*C8*HW];
__device__ float g_k [NB*C8*HW];
__device__ float g_v [NB*CMID*HW];
__device__ float g_h [NB*OCH*HW];      // 512-ch conv temp
__device__ float g_stats[2*OCH];       // per-channel scale/shift
__device__ float g_S[256];             // 16x16 gram
__device__ float g_Wm[256];            // 16x16 attention weights

// ---------------------------------------------------------------------------
// Tiled implicit-GEMM: out[b,m,hw] = sum_k W[m,k] * im2col(in)[k, b*HW+hw]
// Handles 3x3 (K = Cin*9, pad=1) and 1x1 (K = Cin). Input may be a concat of
// up to 3 channel segments (p0:c0, p1:c1, p2:c2). Optional bias.
// Tile: 128(M) x 128(N) x 16(K); 256 threads; 8x8 per thread (interleaved).
// ---------------------------------------------------------------------------
__global__ __launch_bounds__(256) void gemm_conv_kernel(
    const float* __restrict__ Wt,
    const float* __restrict__ p0, const float* __restrict__ p1, const float* __restrict__ p2,
    int c0, int c1, int c2,
    int M, int Cin, int is3x3,
    const float* __restrict__ bias,
    float* __restrict__ out)
{
    __shared__ float As[16][128];
    __shared__ float Bs[16][128];

    const int tid = threadIdx.x;
    const int tx = tid & 15, ty = tid >> 4;
    const int m0 = blockIdx.y * 128;
    const int n0 = blockIdx.x * 128;
    const int K  = is3x3 ? Cin * 9 : Cin;

    float acc[8][8];
#pragma unroll
    for (int i = 0; i < 8; i++)
#pragma unroll
        for (int j = 0; j < 8; j++) acc[i][j] = 0.f;

    // B-load thread mapping: nl in [0,128), kbB in {0,8}
    const int nl  = tid & 127;
    const int nglob = n0 + nl;
    const int bb  = nglob / HW;
    const int hw  = nglob - bb * HW;
    const int yy0 = hw / WW;
    const int xx0 = hw - yy0 * WW;
    const int kbB = (tid >> 7) * 8;
    // A-load thread mapping: ml in [0,128), kbA in {0,8}
    const int ml  = tid >> 1;
    const int kbA = (tid & 1) * 8;

    for (int k0 = 0; k0 < K; k0 += 16) {
        // ---- load A tile (weights) ----
        {
            int m = m0 + ml;
            const float* wp = Wt + (size_t)m * K + (k0 + kbA);
#pragma unroll
            for (int i = 0; i < 8; i++)
                As[kbA + i][ml] = (m < M) ? wp[i] : 0.f;
        }
        // ---- load B tile (im2col gather) ----
        {
#pragma unroll
            for (int i = 0; i < 8; i++) {
                int kg = k0 + kbB + i;
                int ci, yq, xq;
                if (is3x3) {
                    ci = kg / 9;
                    int t9 = kg - ci * 9;
                    int ky = t9 / 3;
                    yq = yy0 + ky - 1;
                    xq = xx0 + (t9 - ky * 3) - 1;
                } else { ci = kg; yq = yy0; xq = xx0; }
                float val = 0.f;
                if (yq >= 0 && yq < HH && xq >= 0 && xq < WW) {
                    const float* src; int cl, cn;
                    if (ci < c0)           { src = p0; cl = ci;            cn = c0; }
                    else if (ci < c0 + c1) { src = p1; cl = ci - c0;       cn = c1; }
                    else                   { src = p2; cl = ci - c0 - c1;  cn = c2; }
                    val = src[((size_t)(bb * cn + cl) * HH + yq) * WW + xq];
                }
                Bs[kbB + i][nl] = val;
            }
        }
        __syncthreads();

#pragma unroll
        for (int kk = 0; kk < 16; kk++) {
            float a[8], bq[8];
#pragma unroll
            for (int i = 0; i < 8; i++) a[i]  = As[kk][ty + 16 * i];
#pragma unroll
            for (int j = 0; j < 8; j++) bq[j] = Bs[kk][tx + 16 * j];
#pragma unroll
            for (int i = 0; i < 8; i++)
#pragma unroll
                for (int j = 0; j < 8; j++)
                    acc[i][j] = fmaf(a[i], bq[j], acc[i][j]);
        }
        __syncthreads();
    }

    // ---- store ----
#pragma unroll
    for (int i = 0; i < 8; i++) {
        int m = m0 + ty + 16 * i;
        if (m >= M) continue;
        float bval = bias ? bias[m] : 0.f;
#pragma unroll
        for (int j = 0; j < 8; j++) {
            int n = n0 + tx + 16 * j;
            int b = n / HW;
            int hw2 = n - b * HW;
            out[((size_t)(b * M + m)) * HW + hw2] = acc[i][j] + bval;
        }
    }
}

// ---------------------------------------------------------------------------
// BN stats: per-channel mean/var over (B, H, W) -> folded scale/shift
// One block (256 threads) per channel.
// ---------------------------------------------------------------------------
__global__ void bn_stats_kernel(const float* __restrict__ x,
                                const float* __restrict__ g,
                                const float* __restrict__ bta,
                                float* __restrict__ stats, int C)
{
    int c = blockIdx.x;
    int tid = threadIdx.x;
    float s = 0.f, sq = 0.f;
    for (int i = tid; i < NB * HW; i += 256) {
        int bb = i / HW;
        int hw = i - bb * HW;
        float v = x[((size_t)(bb * C + c)) * HW + hw];
        s += v; sq += v * v;
    }
    __shared__ float sh1[256], sh2[256];
    sh1[tid] = s; sh2[tid] = sq;
    __syncthreads();
    for (int st = 128; st; st >>= 1) {
        if (tid < st) { sh1[tid] += sh1[tid + st]; sh2[tid] += sh2[tid + st]; }
        __syncthreads();
    }
    if (tid == 0) {
        float n   = (float)(NB * HW);
        float m   = sh1[0] / n;
        float var = sh2[0] / n - m * m;
        float sc  = g[c] * rsqrtf(var + 1e-5f);
        stats[2 * c]     = sc;
        stats[2 * c + 1] = bta[c] - m * sc;
    }
}

__global__ void bn_apply_kernel(const float* __restrict__ x,
                                const float* __restrict__ stats,
                                float* __restrict__ y, int C, int total)
{
    int i = blockIdx.x * 256 + threadIdx.x;
    if (i < total) {
        int c = (i / HW) % C;
        y[i] = fmaxf(fmaf(x[i], stats[2 * c], stats[2 * c + 1]), 0.f);
    }
}

// ---------------------------------------------------------------------------
// Criss-cross attention core. One block per (b, h, w); 256 threads.
// out = gamma * (oH + oW) + xin
// ---------------------------------------------------------------------------
__global__ void cc_core_kernel(const float* __restrict__ q,
                               const float* __restrict__ kk_,
                               const float* __restrict__ v,
                               const float* __restrict__ xin,
                               const float* __restrict__ gamma,
                               float* __restrict__ out)
{
    int w = blockIdx.x, h = blockIdx.y, b = blockIdx.z;
    int tid = threadIdx.x;
    __shared__ float qs[32];
    __shared__ float lg[128];
    __shared__ float red[128];

    if (tid < 32) qs[tid] = q[((b * C8 + tid) * HH + h) * WW + w];
    __syncthreads();

    if (tid < 128) {
        float val = NEG_INF;
        if (tid < 48) {
            int g = tid;
            if (g != h) {
                float s = 0.f;
#pragma unroll
                for (int c = 0; c < 32; c++)
                    s += qs[c] * kk_[((b * C8 + c) * HH + g) * WW + w];
                val = s;
            }
        } else if (tid < 96) {
            int v2 = tid - 48;
            float s = 0.f;
#pragma unroll
            for (int c = 0; c < 32; c++)
                s += qs[c] * kk_[((b * C8 + c) * HH + h) * WW + v2];
            val = s;
        }
        lg[tid]  = val;
        red[tid] = val;
    } else if (tid < 256) {
        // nothing
    }
    __syncthreads();
    // max reduce over 128
    for (int st = 64; st; st >>= 1) {
        if (tid < st) red[tid] = fmaxf(red[tid], red[tid + st]);
        __syncthreads();
    }
    float mx = red[0];
    __syncthreads();
    if (tid < 128) {
        float e = expf(lg[tid] - mx);  // -inf -> 0
        lg[tid]  = e;
        red[tid] = e;
    }
    __syncthreads();
    for (int st = 64; st; st >>= 1) {
        if (tid < st) red[tid] += red[tid + st];
        __syncthreads();
    }
    float inv = 1.f / red[0];

    // phase 3: one output channel per thread
    int c = tid;
    float o = 0.f;
#pragma unroll 4
    for (int g = 0; g < 48; g++)
        o += lg[g] * v[((b * CMID + c) * HH + g) * WW + w];
#pragma unroll 4
    for (int v2 = 0; v2 < 48; v2++)
        o += lg[48 + v2] * v[((b * CMID + c) * HH + h) * WW + v2];
    o *= inv;
    size_t oi = ((size_t)(b * CMID + c) * HH + h) * WW + w;
    out[oi] = gamma[0] * o + xin[oi];
}

// ---------------------------------------------------------------------------
// "my" (grid) attention: gram S[b1,b2] = q[b1] . k[b2]  (len 73728)
// ---------------------------------------------------------------------------
__global__ void gram_kernel(const float* __restrict__ q,
                            const float* __restrict__ k,
                            float* __restrict__ S)
{
    int b1 = blockIdx.x >> 4, b2 = blockIdx.x & 15;
    const float* qp = q + (size_t)b1 * (C8 * HW);
    const float* kp = k + (size_t)b2 * (C8 * HW);
    int tid = threadIdx.x;
    float s = 0.f;
    for (int i = tid; i < C8 * HW; i += 256) s += qp[i] * kp[i];
    __shared__ float sh[256];
    sh[tid] = s;
    __syncthreads();
    for (int st = 128; st; st >>= 1) {
        if (tid < st) sh[tid] += sh[tid + st];
        __syncthreads();
    }
    if (tid == 0) S[blockIdx.x] = sh[0];
}

// 16 threads: per-batch masked 8-way softmax -> dense 16x16 weight matrix
__global__ void myw_kernel(const float* __restrict__ S, float* __restrict__ Wm)
{
    int b1 = threadIdx.x;
    if (b1 < 16) {
        int gh = b1 >> 2, gw = b1 & 3;
        float l[8];
        for (int j = 0; j < 4; j++) {
            int b2 = j * 4 + gw;
            l[j] = (j == gh) ? NEG_INF : S[b1 * 16 + b2];
        }
        for (int j = 0; j < 4; j++) l[4 + j] = S[b1 * 16 + gh * 4 + j];
        float mx = NEG_INF;
        for (int j = 0; j < 8; j++) mx = fmaxf(mx, l[j]);
        float sm = 0.f;
        for (int j = 0; j < 8; j++) { l[j] = expf(l[j] - mx); sm += l[j]; }
        float inv = 1.f / sm;
        float w[16];
        for (int i = 0; i < 16; i++) w[i] = 0.f;
        for (int j = 0; j < 4; j++) w[j * 4 + gw] += l[j] * inv;       // column mates
        for (int j = 0; j < 4; j++) w[gh * 4 + j] += l[4 + j] * inv;   // row mates
        for (int i = 0; i < 16; i++) Wm[b1 * 16 + i] = w[i];
    }
}

// out[b1, n] = gamma * sum_b2 W[b1,b2] * v[b2, n] + xin[b1, n]
__global__ void my_combine_kernel(const float* __restrict__ v,
                                  const float* __restrict__ Wm,
                                  const float* __restrict__ xin,
                                  const float* __restrict__ gamma,
                                  float* __restrict__ out)
{
    __shared__ float ws[256];
    if (threadIdx.x < 256) ws[threadIdx.x] = Wm[threadIdx.x];
    __syncthreads();
    const int PB = CMID * HW;  // 589824 per batch
    int n = blockIdx.x * 256 + threadIdx.x;
    if (n < PB) {
        float vv[16];
#pragma unroll
        for (int b = 0; b < 16; b++) vv[b] = v[(size_t)b * PB + n];
        float gm = gamma[0];
#pragma unroll
        for (int b1 = 0; b1 < 16; b1++) {
            float o = 0.f;
#pragma unroll
            for (int b2 = 0; b2 < 16; b2++) o += ws[b1 * 16 + b2] * vv[b2];
            out[(size_t)b1 * PB + n] = gm * o + xin[(size_t)b1 * PB + n];
        }
    }
}

// ---------------------------------------------------------------------------
// Host orchestration
// ---------------------------------------------------------------------------
extern "C" void kernel_launch(void* const* d_in, const int* in_sizes, int n_in,
                              void* d_out, int out_size)
{
    const float* x      = (const float*)d_in[0];
    const float* w_a    = (const float*)d_in[1];
    const float* g_a    = (const float*)d_in[2];
    const float* b_a    = (const float*)d_in[3];
    const float* ccq_w  = (const float*)d_in[4];
    const float* ccq_b  = (const float*)d_in[5];
    const float* cck_w  = (const float*)d_in[6];
    const float* cck_b  = (const float*)d_in[7];
    const float* ccv_w  = (const float*)d_in[8];
    const float* ccv_b  = (const float*)d_in[9];
    const float* cc_gm  = (const float*)d_in[10];
    const float* w_b    = (const float*)d_in[11];
    const float* g_b    = (const float*)d_in[12];
    const float* b_b    = (const float*)d_in[13];
    const float* w_m1   = (const float*)d_in[14];
    const float* g_m1   = (const float*)d_in[15];
    const float* b_m1   = (const float*)d_in[16];
    const float* myq_w  = (const float*)d_in[17];
    const float* myq_b  = (const float*)d_in[18];
    const float* myk_w  = (const float*)d_in[19];
    const float* myk_b  = (const float*)d_in[20];
    const float* myv_w  = (const float*)d_in[21];
    const float* myv_b  = (const float*)d_in[22];
    const float* my_gm  = (const float*)d_in[23];
    const float* w_m2   = (const float*)d_in[24];
    const float* g_m2   = (const float*)d_in[25];
    const float* b_m2   = (const float*)d_in[26];
    const float* w_c    = (const float*)d_in[27];
    const float* g_c    = (const float*)d_in[28];
    const float* b_c    = (const float*)d_in[29];
    const float* w_cls  = (const float*)d_in[30];
    const float* b_cls  = (const float*)d_in[31];

    float *pt0, *pcc, *pmy, *pt1, *pq, *pk, *pv, *ph, *pst, *pS, *pWm;
    cudaGetSymbolAddress((void**)&pt0, g_t0);
    cudaGetSymbolAddress((void**)&pcc, g_cc);
    cudaGetSymbolAddress((void**)&pmy, g_my);
    cudaGetSymbolAddress((void**)&pt1, g_t1);
    cudaGetSymbolAddress((void**)&pq,  g_q);
    cudaGetSymbolAddress((void**)&pk,  g_k);
    cudaGetSymbolAddress((void**)&pv,  g_v);
    cudaGetSymbolAddress((void**)&ph,  g_h);
    cudaGetSymbolAddress((void**)&pst, g_stats);
    cudaGetSymbolAddress((void**)&pS,  g_S);
    cudaGetSymbolAddress((void**)&pWm, g_Wm);

    const dim3 blk(256);
    const int NT = NTOT / 128;  // 288 N-tiles

    // ---- conv_a: x -> t0 (256 ch), BN -> cc ----
    gemm_conv_kernel<<<dim3(NT, 2), blk>>>(w_a, x, x, x, CIN, 0, 0, CMID, CIN, 1, nullptr, pt0);
    bn_stats_kernel<<<CMID, blk>>>(pt0, g_a, b_a, pst, CMID);
    bn_apply_kernel<<<(NB*CMID*HW + 255)/256, blk>>>(pt0, pst, pcc, CMID, NB*CMID*HW);

    // ---- conv_m1: x -> t0, BN -> my ----
    gemm_conv_kernel<<<dim3(NT, 2), blk>>>(w_m1, x, x, x, CIN, 0, 0, CMID, CIN, 1, nullptr, pt0);
    bn_stats_kernel<<<CMID, blk>>>(pt0, g_m1, b_m1, pst, CMID);
    bn_apply_kernel<<<(NB*CMID*HW + 255)/256, blk>>>(pt0, pst, pmy, CMID, NB*CMID*HW);

    // ---- cc attention x2 (ping-pong cc <-> t1) ----
    {
        float* ca = pcc; float* cb = pt1;
        for (int it = 0; it < 2; it++) {
            gemm_conv_kernel<<<dim3(NT, 1), blk>>>(ccq_w, ca, ca, ca, CMID, 0, 0, C8,   CMID, 0, ccq_b, pq);
            gemm_conv_kernel<<<dim3(NT, 1), blk>>>(cck_w, ca, ca, ca, CMID, 0, 0, C8,   CMID, 0, cck_b, pk);
            gemm_conv_kernel<<<dim3(NT, 2), blk>>>(ccv_w, ca, ca, ca, CMID, 0, 0, CMID, CMID, 0, ccv_b, pv);
            cc_core_kernel<<<dim3(WW, HH, NB), blk>>>(pq, pk, pv, ca, cc_gm, cb);
            float* tmp = ca; ca = cb; cb = tmp;
        }
        // result back in pcc (even number of swaps)
    }

    // ---- my attention x2 (ping-pong my <-> t1) ----
    {
        float* ma = pmy; float* mb = pt1;
        for (int it = 0; it < 2; it++) {
            gemm_conv_kernel<<<dim3(NT, 1), blk>>>(myq_w, ma, ma, ma, CMID, 0, 0, C8,   CMID, 0, myq_b, pq);
            gemm_conv_kernel<<<dim3(NT, 1), blk>>>(myk_w, ma, ma, ma, CMID, 0, 0, C8,   CMID, 0, myk_b, pk);
            gemm_conv_kernel<<<dim3(NT, 2), blk>>>(myv_w, ma, ma, ma, CMID, 0, 0, CMID, CMID, 0, myv_b, pv);
            gram_kernel<<<256, blk>>>(pq, pk, pS);
            myw_kernel<<<1, 32>>>(pS, pWm);
            my_combine_kernel<<<(CMID*HW + 255)/256, blk>>>(pv, pWm, ma, my_gm, mb);
            float* tmp = ma; ma = mb; mb = tmp;
        }
    }

    // ---- conv_b: cc -> t0, BN -> cc ----
    gemm_conv_kernel<<<dim3(NT, 2), blk>>>(w_b, pcc, pcc, pcc, CMID, 0, 0, CMID, CMID, 1, nullptr, pt0);
    bn_stats_kernel<<<CMID, blk>>>(pt0, g_b, b_b, pst, CMID);
    bn_apply_kernel<<<(NB*CMID*HW + 255)/256, blk>>>(pt0, pst, pcc, CMID, NB*CMID*HW);

    // ---- conv_m2: my -> t0, BN -> my ----
    gemm_conv_kernel<<<dim3(NT, 2), blk>>>(w_m2, pmy, pmy, pmy, CMID, 0, 0, CMID, CMID, 1, nullptr, pt0);
    bn_stats_kernel<<<CMID, blk>>>(pt0, g_m2, b_m2, pst, CMID);
    bn_apply_kernel<<<(NB*CMID*HW + 255)/256, blk>>>(pt0, pst, pmy, CMID, NB*CMID*HW);

    // ---- conv_c: concat(x, cc, my) 1536 ch -> h (512 ch), BN in-place ----
    gemm_conv_kernel<<<dim3(NT, 4), blk>>>(w_c, x, pcc, pmy, CIN, CMID, CMID,
                                           OCH, CIN + 2*CMID, 1, nullptr, ph);
    bn_stats_kernel<<<OCH, blk>>>(ph, g_c, b_c, pst, OCH);
    bn_apply_kernel<<<(NB*OCH*HW + 255)/256, blk>>>(ph, pst, ph, OCH, NB*OCH*HW);

    // ---- classifier 1x1: h -> out (21 ch) ----
    gemm_conv_kernel<<<dim3(NT, 1), blk>>>(w_cls, ph, ph, ph, OCH, 0, 0,
                                           NCLS, OCH, 0, b_cls, (float*)d_out);
}

// round 5
// speedup vs baseline: 2.6088x; 2.6034x over previous
#include <cuda_runtime.h>
#include <cuda_bf16.h>
#include <math.h>
#include <stdint.h>

#define NB   16
#define CIN  1024
#define CMID 256
#define C8   32
#define HH   48
#define WW   48
#define HW   (HH*WW)
#define NTOT (NB*HW)
#define OCH  512
#define NCLS 21
#define NEG_INF (__int_as_float(0xff800000))

// ---------------- static scratch ----------------
__device__ float g_t0[NB*CMID*HW];
__device__ float g_cc[NB*CMID*HW];
__device__ float g_my[NB*CMID*HW];
__device__ float g_t1[NB*CMID*HW];
__device__ float g_q [NB*C8*HW];
__device__ float g_k [NB*C8*HW];
__device__ float g_v [NB*CMID*HW];
__device__ float g_h [NB*OCH*HW];
__device__ float g_stats[2*OCH];
__device__ float g_S[256];
__device__ float g_Wm[256];

__device__ __align__(256) __nv_bfloat16 g_XCh[(size_t)NTOT*1536];
__device__ __align__(256) __nv_bfloat16 g_XCl[(size_t)NTOT*1536];
__device__ __align__(256) __nv_bfloat16 g_ACTh[(size_t)NTOT*256];
__device__ __align__(256) __nv_bfloat16 g_ACTl[(size_t)NTOT*256];
__device__ __align__(256) __nv_bfloat16 g_WAh[256*9216],  g_WAl[256*9216];
__device__ __align__(256) __nv_bfloat16 g_WM1h[256*9216], g_WM1l[256*9216];
__device__ __align__(256) __nv_bfloat16 g_WBh[256*2304],  g_WBl[256*2304];
__device__ __align__(256) __nv_bfloat16 g_WM2h[256*2304], g_WM2l[256*2304];
__device__ __align__(256) __nv_bfloat16 g_WCh[512*13824], g_WCl[512*13824];

// ---------------- helpers ----------------
__device__ __forceinline__ uint32_t smem_u32(const void* p){
    uint32_t a;
    asm("{ .reg .u64 t; cvta.to.shared.u64 t, %1; cvt.u32.u64 %0, t; }" : "=r"(a) : "l"(p));
    return a;
}
__device__ __forceinline__ void cp16(uint32_t s, const void* g, uint32_t sz){
    asm volatile("cp.async.cg.shared.global [%0], [%1], 16, %2;" :: "r"(s), "l"(g), "r"(sz) : "memory");
}
__device__ __forceinline__ void ldmx4(uint32_t* r, uint32_t a){
    asm volatile("ldmatrix.sync.aligned.m8n8.x4.shared.b16 {%0,%1,%2,%3}, [%4];"
        : "=r"(r[0]),"=r"(r[1]),"=r"(r[2]),"=r"(r[3]) : "r"(a));
}
__device__ __forceinline__ void mma_bf16(float* d, const uint32_t* a, const uint32_t* b){
    asm volatile("mma.sync.aligned.m16n8k16.row.col.f32.bf16.bf16.f32 "
        "{%0,%1,%2,%3}, {%4,%5,%6,%7}, {%8,%9}, {%0,%1,%2,%3};"
        : "+f"(d[0]),"+f"(d[1]),"+f"(d[2]),"+f"(d[3])
        : "r"(a[0]),"r"(a[1]),"r"(a[2]),"r"(a[3]), "r"(b[0]),"r"(b[1]));
}

// ---------------- NCHW fp32 -> NHWC bf16 hi/lo ----------------
__global__ void to_nhwc_kernel(const float* __restrict__ src,
                               __nv_bfloat16* __restrict__ hi,
                               __nv_bfloat16* __restrict__ lo,
                               int C, int RS, int co)
{
    __shared__ float t[32][33];
    int hw0 = blockIdx.x * 32, c0 = blockIdx.y * 32, b = blockIdx.z;
    int lx = threadIdx.x, ly = threadIdx.y;
    for (int i = ly; i < 32; i += 8)
        t[i][lx] = src[((size_t)(b * C + c0 + i)) * HW + hw0 + lx];
    __syncthreads();
    for (int i = ly; i < 32; i += 8){
        float v = t[lx][i];
        __nv_bfloat16 h = __float2bfloat16(v);
        size_t o = ((size_t)(b * HW + hw0 + i)) * RS + co + c0 + lx;
        hi[o] = h;
        lo[o] = __float2bfloat16(v - __bfloat162float(h));
    }
}

// ---------------- weight prep: [M,C,3,3] -> [M, t*C+c] hi/lo ----------------
__global__ void wprep_kernel(const float* __restrict__ w,
                             __nv_bfloat16* __restrict__ hi,
                             __nv_bfloat16* __restrict__ lo,
                             int M, int C, int ntaps)
{
    int i = blockIdx.x * 256 + threadIdx.x;
    int Kt = ntaps * C;
    if (i < M * Kt){
        int m = i / Kt; int rest = i - m * Kt; int t = rest / C; int c = rest - t * C;
        float v = w[(size_t)(m * C + c) * ntaps + t];
        __nv_bfloat16 h = __float2bfloat16(v);
        hi[i] = h;
        lo[i] = __float2bfloat16(v - __bfloat162float(h));
    }
}

// ---------------- mma.sync implicit-GEMM conv (bf16 split x3, fp32 acc) -----
// Tile 128(M) x 128(N pixels) x 32(K). 256 threads, 8 warps (2 M x 4 N),
// warp tile 64x32. Smem per buffer: Ah/Al/Bh/Bl 128 rows x 80B (32 bf16 + pad).
#define MC_SMEM (2*4*128*80)   // 81920

struct McCtx {
    const __nv_bfloat16 *Ahi, *Alo, *Bhi, *Blo;
    int C, ntaps, Ktot, cpT, RS, co;
    int r, half, b, yy, xx, am;
    uint32_t sb;
};

__device__ __forceinline__ void mc_load(const McCtx& cx, int cc, int buf)
{
    int t   = cc / cx.cpT;
    int ci0 = (cc - t * cx.cpT) << 5;
    uint32_t dst = cx.sb + buf * 40960 + cx.r * 80 + cx.half * 32;
    {   // A (always valid: M multiple of 128)
        size_t off = (size_t)cx.am * cx.Ktot + t * cx.C + ci0 + cx.half * 16;
        cp16(dst,              cx.Ahi + off,     16);
        cp16(dst + 16,         cx.Ahi + off + 8, 16);
        cp16(dst + 10240,      cx.Alo + off,     16);
        cp16(dst + 10240 + 16, cx.Alo + off + 8, 16);
    }
    {   // B (halo may be out of bounds -> zero fill)
        int dy = 0, dx = 0;
        if (cx.ntaps == 9){ dy = t / 3 - 1; dx = t - (t / 3) * 3 - 1; }
        int ys = cx.yy + dy, xs = cx.xx + dx;
        bool bv = (ys >= 0 && ys < HH && xs >= 0 && xs < WW);
        size_t off = bv ? ((size_t)(cx.b * HW + ys * WW + xs) * cx.RS + cx.co + ci0 + cx.half * 16) : 0;
        uint32_t sz = bv ? 16u : 0u;
        cp16(dst + 20480,      cx.Bhi + off,     sz);
        cp16(dst + 20480 + 16, cx.Bhi + off + 8, sz);
        cp16(dst + 30720,      cx.Blo + off,     sz);
        cp16(dst + 30720 + 16, cx.Blo + off + 8, sz);
    }
}

__global__ __launch_bounds__(256) void mma_conv_kernel(
    const __nv_bfloat16* __restrict__ Ahi, const __nv_bfloat16* __restrict__ Alo,
    const __nv_bfloat16* __restrict__ Bhi, const __nv_bfloat16* __restrict__ Blo,
    int M, int C, int ntaps, int RS, int co,
    float* __restrict__ out)
{
    extern __shared__ char dynsm[];
    const int tid = threadIdx.x, lane = tid & 31, wid = tid >> 5;
    const int wm = wid & 1, wn = wid >> 1;
    const int m0 = blockIdx.y * 128;
    const int n0 = blockIdx.x * 128;

    McCtx cx;
    cx.Ahi = Ahi; cx.Alo = Alo; cx.Bhi = Bhi; cx.Blo = Blo;
    cx.C = C; cx.ntaps = ntaps; cx.Ktot = ntaps * C; cx.cpT = C >> 5;
    cx.RS = RS; cx.co = co;
    cx.r = tid >> 1; cx.half = tid & 1;
    {
        int n = n0 + cx.r;
        cx.b = n / HW;
        int hw = n - cx.b * HW;
        cx.yy = hw / WW;
        cx.xx = hw - cx.yy * WW;
    }
    cx.am = m0 + cx.r;
    cx.sb = smem_u32(dynsm);

    float acc[4][4][4];
#pragma unroll
    for (int i = 0; i < 4; i++)
#pragma unroll
        for (int j = 0; j < 4; j++)
#pragma unroll
            for (int q = 0; q < 4; q++) acc[i][j][q] = 0.f;

    const int NC = cx.Ktot >> 5;

    mc_load(cx, 0, 0);
    asm volatile("cp.async.commit_group;" ::: "memory");

    const uint32_t aRowOff = (uint32_t)(lane & 15) * 80;
    const uint32_t aColOff = (uint32_t)(lane >> 4) * 16;
    const uint32_t bRowOff = (uint32_t)((lane & 7) + ((lane >> 4) << 3)) * 80;
    const uint32_t bColOff = (uint32_t)((lane >> 3) & 1) * 16;

    for (int cc = 0; cc < NC; cc++){
        int buf = cc & 1;
        if (cc + 1 < NC){
            mc_load(cx, cc + 1, (cc + 1) & 1);
            asm volatile("cp.async.commit_group;" ::: "memory");
            asm volatile("cp.async.wait_group 1;" ::: "memory");
        } else {
            asm volatile("cp.async.wait_group 0;" ::: "memory");
        }
        __syncthreads();
        uint32_t base = cx.sb + buf * 40960;
#pragma unroll
        for (int k16 = 0; k16 < 2; k16++){
            uint32_t ac = (uint32_t)k16 * 32 + aColOff;
            uint32_t bc = (uint32_t)k16 * 32 + bColOff;
            uint32_t ah[4][4], al[4][4], bh[2][4], bl[2][4];
#pragma unroll
            for (int mi = 0; mi < 4; mi++){
                uint32_t ad = base + (uint32_t)(wm * 64 + mi * 16) * 80 + aRowOff + ac;
                ldmx4(ah[mi], ad);
                ldmx4(al[mi], ad + 10240);
            }
#pragma unroll
            for (int ng = 0; ng < 2; ng++){
                uint32_t bd = base + 20480 + (uint32_t)(wn * 32 + ng * 16) * 80 + bRowOff + bc;
                ldmx4(bh[ng], bd);
                ldmx4(bl[ng], bd + 10240);
            }
#pragma unroll
            for (int mi = 0; mi < 4; mi++){
#pragma unroll
                for (int ni = 0; ni < 4; ni++){
                    const uint32_t* bhp = &bh[ni >> 1][(ni & 1) * 2];
                    const uint32_t* blp = &bl[ni >> 1][(ni & 1) * 2];
                    mma_bf16(acc[mi][ni], ah[mi], bhp);
                    mma_bf16(acc[mi][ni], ah[mi], blp);
                    mma_bf16(acc[mi][ni], al[mi], bhp);
                }
            }
        }
        __syncthreads();
    }

    // epilogue: direct NCHW fp32 stores
    int tb = n0 / HW;
    int hw0 = n0 - tb * HW;
#pragma unroll
    for (int mi = 0; mi < 4; mi++){
        int mrow = m0 + wm * 64 + mi * 16 + (lane >> 2);
#pragma unroll
        for (int ni = 0; ni < 4; ni++){
            int col = hw0 + wn * 32 + ni * 8 + (lane & 3) * 2;
            float2 v0 = make_float2(acc[mi][ni][0], acc[mi][ni][1]);
            float2 v1 = make_float2(acc[mi][ni][2], acc[mi][ni][3]);
            *(float2*)&out[((size_t)(tb * M + mrow)) * HW + col]     = v0;
            *(float2*)&out[((size_t)(tb * M + mrow + 8)) * HW + col] = v1;
        }
    }
}

// ---------------- fp32 GEMM (qkv / classifier) ----------------
__global__ __launch_bounds__(256) void gemm_conv_kernel(
    const float* __restrict__ Wt, const float* __restrict__ p0,
    int M, int Cin, const float* __restrict__ bias, float* __restrict__ out)
{
    __shared__ float As[16][128];
    __shared__ float Bs[16][128];
    const int tid = threadIdx.x;
    const int tx = tid & 15, ty = tid >> 4;
    const int m0 = blockIdx.y * 128;
    const int n0 = blockIdx.x * 128;
    float acc[8][8];
#pragma unroll
    for (int i = 0; i < 8; i++)
#pragma unroll
        for (int j = 0; j < 8; j++) acc[i][j] = 0.f;
    const int nl = tid & 127;
    const int nglob = n0 + nl;
    const int bb = nglob / HW;
    const int hw = nglob - bb * HW;
    const int kbB = (tid >> 7) * 8;
    const int ml = tid >> 1;
    const int kbA = (tid & 1) * 8;
    for (int k0 = 0; k0 < Cin; k0 += 16){
        int m = m0 + ml;
        const float* wp = Wt + (size_t)m * Cin + (k0 + kbA);
#pragma unroll
        for (int i = 0; i < 8; i++)
            As[kbA + i][ml] = (m < M) ? wp[i] : 0.f;
#pragma unroll
        for (int i = 0; i < 8; i++)
            Bs[kbB + i][nl] = p0[((size_t)(bb * Cin + k0 + kbB + i)) * HW + hw];
        __syncthreads();
#pragma unroll
        for (int kk = 0; kk < 16; kk++){
            float a[8], bq[8];
#pragma unroll
            for (int i = 0; i < 8; i++) a[i]  = As[kk][ty + 16 * i];
#pragma unroll
            for (int j = 0; j < 8; j++) bq[j] = Bs[kk][tx + 16 * j];
#pragma unroll
            for (int i = 0; i < 8; i++)
#pragma unroll
                for (int j = 0; j < 8; j++)
                    acc[i][j] = fmaf(a[i], bq[j], acc[i][j]);
        }
        __syncthreads();
    }
#pragma unroll
    for (int i = 0; i < 8; i++){
        int m = m0 + ty + 16 * i;
        if (m >= M) continue;
        float bval = bias ? bias[m] : 0.f;
#pragma unroll
        for (int j = 0; j < 8; j++){
            int n = n0 + tx + 16 * j;
            int b = n / HW;
            int hw2 = n - b * HW;
            out[((size_t)(b * M + m)) * HW + hw2] = acc[i][j] + bval;
        }
    }
}

// ---------------- BatchNorm ----------------
__global__ void bn_stats_kernel(const float* __restrict__ x,
                                const float* __restrict__ g,
                                const float* __restrict__ bta,
                                float* __restrict__ stats, int C)
{
    int c = blockIdx.x, tid = threadIdx.x;
    float s = 0.f, sq = 0.f;
    for (int i = tid; i < NB * HW; i += 256){
        int bb = i / HW;
        float v = x[((size_t)(bb * C + c)) * HW + (i - bb * HW)];
        s += v; sq += v * v;
    }
    __shared__ float sh1[256], sh2[256];
    sh1[tid] = s; sh2[tid] = sq;
    __syncthreads();
    for (int st = 128; st; st >>= 1){
        if (tid < st){ sh1[tid] += sh1[tid + st]; sh2[tid] += sh2[tid + st]; }
        __syncthreads();
    }
    if (tid == 0){
        float n = (float)(NB * HW);
        float m = sh1[0] / n;
        float var = sh2[0] / n - m * m;
        float sc = g[c] * rsqrtf(var + 1e-5f);
        stats[2 * c] = sc;
        stats[2 * c + 1] = bta[c] - m * sc;
    }
}

__global__ void bn_apply_kernel(const float* __restrict__ x,
                                const float* __restrict__ stats,
                                float* __restrict__ y, int C, int total)
{
    int i = blockIdx.x * 256 + threadIdx.x;
    if (i < total){
        int c = (i / HW) % C;
        y[i] = fmaxf(fmaf(x[i], stats[2 * c], stats[2 * c + 1]), 0.f);
    }
}

// ---------------- criss-cross attention ----------------
__global__ void cc_core_kernel(const float* __restrict__ q,
                               const float* __restrict__ kk_,
                               const float* __restrict__ v,
                               const float* __restrict__ xin,
                               const float* __restrict__ gamma,
                               float* __restrict__ out)
{
    int w = blockIdx.x, h = blockIdx.y, b = blockIdx.z;
    int tid = threadIdx.x;
    __shared__ float qs[32];
    __shared__ float lg[128];
    __shared__ float red[128];

    if (tid < 32) qs[tid] = q[((b * C8 + tid) * HH + h) * WW + w];
    __syncthreads();

    if (tid < 128){
        float val = NEG_INF;
        if (tid < 48){
            int g = tid;
            if (g != h){
                float s = 0.f;
#pragma unroll
                for (int c = 0; c < 32; c++)
                    s += qs[c] * kk_[((b * C8 + c) * HH + g) * WW + w];
                val = s;
            }
        } else if (tid < 96){
            int v2 = tid - 48;
            float s = 0.f;
#pragma unroll
            for (int c = 0; c < 32; c++)
                s += qs[c] * kk_[((b * C8 + c) * HH + h) * WW + v2];
            val = s;
        }
        lg[tid] = val;
        red[tid] = val;
    }
    __syncthreads();
    for (int st = 64; st; st >>= 1){
        if (tid < st) red[tid] = fmaxf(red[tid], red[tid + st]);
        __syncthreads();
    }
    float mx = red[0];
    __syncthreads();
    if (tid < 128){
        float e = expf(lg[tid] - mx);
        lg[tid] = e;
        red[tid] = e;
    }
    __syncthreads();
    for (int st = 64; st; st >>= 1){
        if (tid < st) red[tid] += red[tid + st];
        __syncthreads();
    }
    float inv = 1.f / red[0];

    int c = tid;
    float o = 0.f;
#pragma unroll 4
    for (int g = 0; g < 48; g++)
        o += lg[g] * v[((b * CMID + c) * HH + g) * WW + w];
#pragma unroll 4
    for (int v2 = 0; v2 < 48; v2++)
        o += lg[48 + v2] * v[((b * CMID + c) * HH + h) * WW + v2];
    o *= inv;
    size_t oi = ((size_t)(b * CMID + c) * HH + h) * WW + w;
    out[oi] = gamma[0] * o + xin[oi];
}

// ---------------- grid attention ----------------
__global__ void gram_kernel(const float* __restrict__ q,
                            const float* __restrict__ k,
                            float* __restrict__ S)
{
    int b1 = blockIdx.x >> 4, b2 = blockIdx.x & 15;
    const float* qp = q + (size_t)b1 * (C8 * HW);
    const float* kp = k + (size_t)b2 * (C8 * HW);
    int tid = threadIdx.x;
    float s = 0.f;
    for (int i = tid; i < C8 * HW; i += 256) s += qp[i] * kp[i];
    __shared__ float sh[256];
    sh[tid] = s;
    __syncthreads();
    for (int st = 128; st; st >>= 1){
        if (tid < st) sh[tid] += sh[tid + st];
        __syncthreads();
    }
    if (tid == 0) S[blockIdx.x] = sh[0];
}

__global__ void myw_kernel(const float* __restrict__ S, float* __restrict__ Wm)
{
    int b1 = threadIdx.x;
    if (b1 < 16){
        int gh = b1 >> 2, gw = b1 & 3;
        float l[8];
        for (int j = 0; j < 4; j++){
            int b2 = j * 4 + gw;
            l[j] = (j == gh) ? NEG_INF : S[b1 * 16 + b2];
        }
        for (int j = 0; j < 4; j++) l[4 + j] = S[b1 * 16 + gh * 4 + j];
        float mx = NEG_INF;
        for (int j = 0; j < 8; j++) mx = fmaxf(mx, l[j]);
        float sm = 0.f;
        for (int j = 0; j < 8; j++){ l[j] = expf(l[j] - mx); sm += l[j]; }
        float inv = 1.f / sm;
        float w[16];
        for (int i = 0; i < 16; i++) w[i] = 0.f;
        for (int j = 0; j < 4; j++) w[j * 4 + gw] += l[j] * inv;
        for (int j = 0; j < 4; j++) w[gh * 4 + j] += l[4 + j] * inv;
        for (int i = 0; i < 16; i++) Wm[b1 * 16 + i] = w[i];
    }
}

__global__ void my_combine_kernel(const float* __restrict__ v,
                                  const float* __restrict__ Wm,
                                  const float* __restrict__ xin,
                                  const float* __restrict__ gamma,
                                  float* __restrict__ out)
{
    __shared__ float ws[256];
    if (threadIdx.x < 256) ws[threadIdx.x] = Wm[threadIdx.x];
    __syncthreads();
    const int PB = CMID * HW;
    int n = blockIdx.x * 256 + threadIdx.x;
    if (n < PB){
        float vv[16];
#pragma unroll
        for (int b = 0; b < 16; b++) vv[b] = v[(size_t)b * PB + n];
        float gm = gamma[0];
#pragma unroll
        for (int b1 = 0; b1 < 16; b1++){
            float o = 0.f;
#pragma unroll
            for (int b2 = 0; b2 < 16; b2++) o += ws[b1 * 16 + b2] * vv[b2];
            out[(size_t)b1 * PB + n] = gm * o + xin[(size_t)b1 * PB + n];
        }
    }
}

// ---------------- host ----------------
extern "C" void kernel_launch(void* const* d_in, const int* in_sizes, int n_in,
                              void* d_out, int out_size)
{
    const float* x      = (const float*)d_in[0];
    const float* w_a    = (const float*)d_in[1];
    const float* g_a    = (const float*)d_in[2];
    const float* b_a    = (const float*)d_in[3];
    const float* ccq_w  = (const float*)d_in[4];
    const float* ccq_b  = (const float*)d_in[5];
    const float* cck_w  = (const float*)d_in[6];
    const float* cck_b  = (const float*)d_in[7];
    const float* ccv_w  = (const float*)d_in[8];
    const float* ccv_b  = (const float*)d_in[9];
    const float* cc_gm  = (const float*)d_in[10];
    const float* w_b    = (const float*)d_in[11];
    const float* g_b    = (const float*)d_in[12];
    const float* b_b    = (const float*)d_in[13];
    const float* w_m1   = (const float*)d_in[14];
    const float* g_m1   = (const float*)d_in[15];
    const float* b_m1   = (const float*)d_in[16];
    const float* myq_w  = (const float*)d_in[17];
    const float* myq_b  = (const float*)d_in[18];
    const float* myk_w  = (const float*)d_in[19];
    const float* myk_b  = (const float*)d_in[20];
    const float* myv_w  = (const float*)d_in[21];
    const float* myv_b  = (const float*)d_in[22];
    const float* my_gm  = (const float*)d_in[23];
    const float* w_m2   = (const float*)d_in[24];
    const float* g_m2   = (const float*)d_in[25];
    const float* b_m2   = (const float*)d_in[26];
    const float* w_c    = (const float*)d_in[27];
    const float* g_c    = (const float*)d_in[28];
    const float* b_c    = (const float*)d_in[29];
    const float* w_cls  = (const float*)d_in[30];
    const float* b_cls  = (const float*)d_in[31];

    cudaFuncSetAttribute(mma_conv_kernel, cudaFuncAttributeMaxDynamicSharedMemorySize, MC_SMEM);

    float *pt0, *pcc, *pmy, *pt1, *pq, *pk, *pv, *ph, *pst, *pS, *pWm;
    cudaGetSymbolAddress((void**)&pt0, g_t0);
    cudaGetSymbolAddress((void**)&pcc, g_cc);
    cudaGetSymbolAddress((void**)&pmy, g_my);
    cudaGetSymbolAddress((void**)&pt1, g_t1);
    cudaGetSymbolAddress((void**)&pq,  g_q);
    cudaGetSymbolAddress((void**)&pk,  g_k);
    cudaGetSymbolAddress((void**)&pv,  g_v);
    cudaGetSymbolAddress((void**)&ph,  g_h);
    cudaGetSymbolAddress((void**)&pst, g_stats);
    cudaGetSymbolAddress((void**)&pS,  g_S);
    cudaGetSymbolAddress((void**)&pWm, g_Wm);

    __nv_bfloat16 *XCh,*XCl,*ACTh,*ACTl;
    __nv_bfloat16 *WAh,*WAl,*WM1h,*WM1l,*WBh,*WBl,*WM2h,*WM2l,*WCh,*WCl;
    cudaGetSymbolAddress((void**)&XCh, g_XCh);   cudaGetSymbolAddress((void**)&XCl, g_XCl);
    cudaGetSymbolAddress((void**)&ACTh, g_ACTh); cudaGetSymbolAddress((void**)&ACTl, g_ACTl);
    cudaGetSymbolAddress((void**)&WAh, g_WAh);   cudaGetSymbolAddress((void**)&WAl, g_WAl);
    cudaGetSymbolAddress((void**)&WM1h, g_WM1h); cudaGetSymbolAddress((void**)&WM1l, g_WM1l);
    cudaGetSymbolAddress((void**)&WBh, g_WBh);   cudaGetSymbolAddress((void**)&WBl, g_WBl);
    cudaGetSymbolAddress((void**)&WM2h, g_WM2h); cudaGetSymbolAddress((void**)&WM2l, g_WM2l);
    cudaGetSymbolAddress((void**)&WCh, g_WCh);   cudaGetSymbolAddress((void**)&WCl, g_WCl);

    const dim3 blk(256);
    const dim3 tr_blk(32, 8);
    const int NT = NTOT / 128;   // 288
    const int TOT_MID = NB*CMID*HW;

    // weight prep
    wprep_kernel<<<(256*9216 + 255)/256, blk>>>(w_a,  WAh,  WAl,  256, 1024, 9);
    wprep_kernel<<<(256*9216 + 255)/256, blk>>>(w_m1, WM1h, WM1l, 256, 1024, 9);
    wprep_kernel<<<(256*2304 + 255)/256, blk>>>(w_b,  WBh,  WBl,  256, 256, 9);
    wprep_kernel<<<(256*2304 + 255)/256, blk>>>(w_m2, WM2h, WM2l, 256, 256, 9);
    wprep_kernel<<<(512*13824 + 255)/256, blk>>>(w_c, WCh,  WCl,  512, 1536, 9);

    // x -> XC[0:1024] (NHWC hi/lo)
    to_nhwc_kernel<<<dim3(HW/32, 1024/32, NB), tr_blk>>>(x, XCh, XCl, 1024, 1536, 0);

    // conv_a, conv_m1 (from x segment of XC)
    mma_conv_kernel<<<dim3(NT, 2), blk, MC_SMEM>>>(WAh, WAl, XCh, XCl, 256, 1024, 9, 1536, 0, pt0);
    bn_stats_kernel<<<CMID, blk>>>(pt0, g_a, b_a, pst, CMID);
    bn_apply_kernel<<<(TOT_MID + 255)/256, blk>>>(pt0, pst, pcc, CMID, TOT_MID);

    mma_conv_kernel<<<dim3(NT, 2), blk, MC_SMEM>>>(WM1h, WM1l, XCh, XCl, 256, 1024, 9, 1536, 0, pt0);
    bn_stats_kernel<<<CMID, blk>>>(pt0, g_m1, b_m1, pst, CMID);
    bn_apply_kernel<<<(TOT_MID + 255)/256, blk>>>(pt0, pst, pmy, CMID, TOT_MID);

    // cc attention x2
    {
        float* ca = pcc; float* cb = pt1;
        for (int it = 0; it < 2; it++){
            gemm_conv_kernel<<<dim3(NT, 1), blk>>>(ccq_w, ca, C8,   CMID, ccq_b, pq);
            gemm_conv_kernel<<<dim3(NT, 1), blk>>>(cck_w, ca, C8,   CMID, cck_b, pk);
            gemm_conv_kernel<<<dim3(NT, 2), blk>>>(ccv_w, ca, CMID, CMID, ccv_b, pv);
            cc_core_kernel<<<dim3(WW, HH, NB), blk>>>(pq, pk, pv, ca, cc_gm, cb);
            float* tmp = ca; ca = cb; cb = tmp;
        }
    }

    // my attention x2
    {
        float* ma = pmy; float* mb = pt1;
        for (int it = 0; it < 2; it++){
            gemm_conv_kernel<<<dim3(NT, 1), blk>>>(myq_w, ma, C8,   CMID, myq_b, pq);
            gemm_conv_kernel<<<dim3(NT, 1), blk>>>(myk_w, ma, C8,   CMID, myk_b, pk);
            gemm_conv_kernel<<<dim3(NT, 2), blk>>>(myv_w, ma, CMID, CMID, myv_b, pv);
            gram_kernel<<<256, blk>>>(pq, pk, pS);
            myw_kernel<<<1, 32>>>(pS, pWm);
            my_combine_kernel<<<(CMID*HW + 255)/256, blk>>>(pv, pWm, ma, my_gm, mb);
            float* tmp = ma; ma = mb; mb = tmp;
        }
    }

    // conv_b (input pcc)
    to_nhwc_kernel<<<dim3(HW/32, 256/32, NB), tr_blk>>>(pcc, ACTh, ACTl, 256, 256, 0);
    mma_conv_kernel<<<dim3(NT, 2), blk, MC_SMEM>>>(WBh, WBl, ACTh, ACTl, 256, 256, 9, 256, 0, pt0);
    bn_stats_kernel<<<CMID, blk>>>(pt0, g_b, b_b, pst, CMID);
    bn_apply_kernel<<<(TOT_MID + 255)/256, blk>>>(pt0, pst, pcc, CMID, TOT_MID);
    to_nhwc_kernel<<<dim3(HW/32, 256/32, NB), tr_blk>>>(pcc, XCh, XCl, 256, 1536, 1024);

    // conv_m2 (input pmy)
    to_nhwc_kernel<<<dim3(HW/32, 256/32, NB), tr_blk>>>(pmy, ACTh, ACTl, 256, 256, 0);
    mma_conv_kernel<<<dim3(NT, 2), blk, MC_SMEM>>>(WM2h, WM2l, ACTh, ACTl, 256, 256, 9, 256, 0, pt0);
    bn_stats_kernel<<<CMID, blk>>>(pt0, g_m2, b_m2, pst, CMID);
    bn_apply_kernel<<<(TOT_MID + 255)/256, blk>>>(pt0, pst, pmy, CMID, TOT_MID);
    to_nhwc_kernel<<<dim3(HW/32, 256/32, NB), tr_blk>>>(pmy, XCh, XCl, 256, 1536, 1280);

    // conv_c (1536 -> 512) + BN
    mma_conv_kernel<<<dim3(NT, 4), blk, MC_SMEM>>>(WCh, WCl, XCh, XCl, 512, 1536, 9, 1536, 0, ph);
    bn_stats_kernel<<<OCH, blk>>>(ph, g_c, b_c, pst, OCH);
    bn_apply_kernel<<<(NB*OCH*HW + 255)/256, blk>>>(ph, pst, ph, OCH, NB*OCH*HW);

    // classifier
    gemm_conv_kernel<<<dim3(NT, 1), blk>>>(w_cls, ph, NCLS, OCH, b_cls, (float*)d_out);
}

// round 6
// speedup vs baseline: 3.7394x; 1.4334x over previous
#include <cuda_runtime.h>
#include <cuda_bf16.h>
#include <math.h>
#include <stdint.h>

#define NB   16
#define CIN  1024
#define CMID 256
#define C8   32
#define HH   48
#define WW   48
#define HW   (HH*WW)
#define NTOT (NB*HW)
#define OCH  512
#define NCLS 21
#define NEG_INF (__int_as_float(0xff800000))

// ---------------- static scratch ----------------
__device__ float g_t0[NB*CMID*HW];
__device__ float g_cc[NB*CMID*HW];
__device__ float g_my[NB*CMID*HW];
__device__ float g_t1[NB*CMID*HW];
__device__ float g_q [NB*C8*HW];
__device__ float g_k [NB*C8*HW];
__device__ float g_v [NB*CMID*HW];
__device__ float g_h [NB*OCH*HW];
__device__ float g_stats[2*OCH];
__device__ float g_S[256];
__device__ float g_Wm[256];
__device__ float g_att[(size_t)NTOT*96];

__device__ __align__(256) __nv_bfloat16 g_XCh[(size_t)NTOT*1536];
__device__ __align__(256) __nv_bfloat16 g_XCl[(size_t)NTOT*1536];
__device__ __align__(256) __nv_bfloat16 g_ACTh[(size_t)NTOT*256];
__device__ __align__(256) __nv_bfloat16 g_ACTl[(size_t)NTOT*256];
__device__ __align__(256) __nv_bfloat16 g_WAh[256*9216],  g_WAl[256*9216];
__device__ __align__(256) __nv_bfloat16 g_WM1h[256*9216], g_WM1l[256*9216];
__device__ __align__(256) __nv_bfloat16 g_WBh[256*2304],  g_WBl[256*2304];
__device__ __align__(256) __nv_bfloat16 g_WM2h[256*2304], g_WM2l[256*2304];
__device__ __align__(256) __nv_bfloat16 g_WCh[512*13824], g_WCl[512*13824];

// ---------------- helpers ----------------
__device__ __forceinline__ uint32_t smem_u32(const void* p){
    uint32_t a;
    asm("{ .reg .u64 t; cvta.to.shared.u64 t, %1; cvt.u32.u64 %0, t; }" : "=r"(a) : "l"(p));
    return a;
}
__device__ __forceinline__ void cp16(uint32_t s, const void* g, uint32_t sz){
    asm volatile("cp.async.cg.shared.global [%0], [%1], 16, %2;" :: "r"(s), "l"(g), "r"(sz) : "memory");
}
__device__ __forceinline__ void ldmx4(uint32_t* r, uint32_t a){
    asm volatile("ldmatrix.sync.aligned.m8n8.x4.shared.b16 {%0,%1,%2,%3}, [%4];"
        : "=r"(r[0]),"=r"(r[1]),"=r"(r[2]),"=r"(r[3]) : "r"(a));
}
__device__ __forceinline__ void mma_bf16(float* d, const uint32_t* a, const uint32_t* b){
    asm volatile("mma.sync.aligned.m16n8k16.row.col.f32.bf16.bf16.f32 "
        "{%0,%1,%2,%3}, {%4,%5,%6,%7}, {%8,%9}, {%0,%1,%2,%3};"
        : "+f"(d[0]),"+f"(d[1]),"+f"(d[2]),"+f"(d[3])
        : "r"(a[0]),"r"(a[1]),"r"(a[2]),"r"(a[3]), "r"(b[0]),"r"(b[1]));
}

// ---------------- NCHW fp32 -> NHWC bf16 hi/lo ----------------
__global__ void to_nhwc_kernel(const float* __restrict__ src,
                               __nv_bfloat16* __restrict__ hi,
                               __nv_bfloat16* __restrict__ lo,
                               int C, int RS, int co)
{
    __shared__ float t[32][33];
    int hw0 = blockIdx.x * 32, c0 = blockIdx.y * 32, b = blockIdx.z;
    int lx = threadIdx.x, ly = threadIdx.y;
    for (int i = ly; i < 32; i += 8)
        t[i][lx] = src[((size_t)(b * C + c0 + i)) * HW + hw0 + lx];
    __syncthreads();
    for (int i = ly; i < 32; i += 8){
        float v = t[lx][i];
        __nv_bfloat16 h = __float2bfloat16(v);
        size_t o = ((size_t)(b * HW + hw0 + i)) * RS + co + c0 + lx;
        hi[o] = h;
        lo[o] = __float2bfloat16(v - __bfloat162float(h));
    }
}

// BN(+ReLU) applied while converting NCHW fp32 -> NHWC bf16 hi/lo
__global__ void bn_to_nhwc_kernel(const float* __restrict__ src,
                                  const float* __restrict__ stats,
                                  __nv_bfloat16* __restrict__ hi,
                                  __nv_bfloat16* __restrict__ lo,
                                  int C, int RS, int co)
{
    __shared__ float t[32][33];
    int hw0 = blockIdx.x * 32, c0 = blockIdx.y * 32, b = blockIdx.z;
    int lx = threadIdx.x, ly = threadIdx.y;
    for (int i = ly; i < 32; i += 8){
        int c = c0 + i;
        float v = src[((size_t)(b * C + c)) * HW + hw0 + lx];
        t[i][lx] = fmaxf(fmaf(v, stats[2*c], stats[2*c+1]), 0.f);
    }
    __syncthreads();
    for (int i = ly; i < 32; i += 8){
        float v = t[lx][i];
        __nv_bfloat16 h = __float2bfloat16(v);
        size_t o = ((size_t)(b * HW + hw0 + i)) * RS + co + c0 + lx;
        hi[o] = h;
        lo[o] = __float2bfloat16(v - __bfloat162float(h));
    }
}

// ---------------- weight prep ----------------
__global__ void wprep_kernel(const float* __restrict__ w,
                             __nv_bfloat16* __restrict__ hi,
                             __nv_bfloat16* __restrict__ lo,
                             int M, int C, int ntaps)
{
    int i = blockIdx.x * 256 + threadIdx.x;
    int Kt = ntaps * C;
    if (i < M * Kt){
        int m = i / Kt; int rest = i - m * Kt; int t = rest / C; int c = rest - t * C;
        float v = w[(size_t)(m * C + c) * ntaps + t];
        __nv_bfloat16 h = __float2bfloat16(v);
        hi[i] = h;
        lo[i] = __float2bfloat16(v - __bfloat162float(h));
    }
}

// ---------------- mma.sync implicit-GEMM conv ----------------
#define MC_SMEM (2*4*128*80)

struct McCtx {
    const __nv_bfloat16 *Ahi, *Alo, *Bhi, *Blo;
    int C, ntaps, Ktot, cpT, RS, co;
    int r, half, b, yy, xx, am;
    uint32_t sb;
};

__device__ __forceinline__ void mc_load(const McCtx& cx, int cc, int buf)
{
    int t   = cc / cx.cpT;
    int ci0 = (cc - t * cx.cpT) << 5;
    uint32_t dst = cx.sb + buf * 40960 + cx.r * 80 + cx.half * 32;
    {
        size_t off = (size_t)cx.am * cx.Ktot + t * cx.C + ci0 + cx.half * 16;
        cp16(dst,              cx.Ahi + off,     16);
        cp16(dst + 16,         cx.Ahi + off + 8, 16);
        cp16(dst + 10240,      cx.Alo + off,     16);
        cp16(dst + 10240 + 16, cx.Alo + off + 8, 16);
    }
    {
        int dy = 0, dx = 0;
        if (cx.ntaps == 9){ dy = t / 3 - 1; dx = t - (t / 3) * 3 - 1; }
        int ys = cx.yy + dy, xs = cx.xx + dx;
        bool bv = (ys >= 0 && ys < HH && xs >= 0 && xs < WW);
        size_t off = bv ? ((size_t)(cx.b * HW + ys * WW + xs) * cx.RS + cx.co + ci0 + cx.half * 16) : 0;
        uint32_t sz = bv ? 16u : 0u;
        cp16(dst + 20480,      cx.Bhi + off,     sz);
        cp16(dst + 20480 + 16, cx.Bhi + off + 8, sz);
        cp16(dst + 30720,      cx.Blo + off,     sz);
        cp16(dst + 30720 + 16, cx.Blo + off + 8, sz);
    }
}

__global__ __launch_bounds__(256) void mma_conv_kernel(
    const __nv_bfloat16* __restrict__ Ahi, const __nv_bfloat16* __restrict__ Alo,
    const __nv_bfloat16* __restrict__ Bhi, const __nv_bfloat16* __restrict__ Blo,
    int M, int C, int ntaps, int RS, int co,
    float* __restrict__ out)
{
    extern __shared__ char dynsm[];
    const int tid = threadIdx.x, lane = tid & 31, wid = tid >> 5;
    const int wm = wid & 1, wn = wid >> 1;
    const int m0 = blockIdx.y * 128;
    const int n0 = blockIdx.x * 128;

    McCtx cx;
    cx.Ahi = Ahi; cx.Alo = Alo; cx.Bhi = Bhi; cx.Blo = Blo;
    cx.C = C; cx.ntaps = ntaps; cx.Ktot = ntaps * C; cx.cpT = C >> 5;
    cx.RS = RS; cx.co = co;
    cx.r = tid >> 1; cx.half = tid & 1;
    {
        int n = n0 + cx.r;
        cx.b = n / HW;
        int hw = n - cx.b * HW;
        cx.yy = hw / WW;
        cx.xx = hw - cx.yy * WW;
    }
    cx.am = m0 + cx.r;
    cx.sb = smem_u32(dynsm);

    float acc[4][4][4];
#pragma unroll
    for (int i = 0; i < 4; i++)
#pragma unroll
        for (int j = 0; j < 4; j++)
#pragma unroll
            for (int q = 0; q < 4; q++) acc[i][j][q] = 0.f;

    const int NC = cx.Ktot >> 5;

    mc_load(cx, 0, 0);
    asm volatile("cp.async.commit_group;" ::: "memory");

    const uint32_t aRowOff = (uint32_t)(lane & 15) * 80;
    const uint32_t aColOff = (uint32_t)(lane >> 4) * 16;
    const uint32_t bRowOff = (uint32_t)((lane & 7) + ((lane >> 4) << 3)) * 80;
    const uint32_t bColOff = (uint32_t)((lane >> 3) & 1) * 16;

    for (int cc = 0; cc < NC; cc++){
        int buf = cc & 1;
        if (cc + 1 < NC){
            mc_load(cx, cc + 1, (cc + 1) & 1);
            asm volatile("cp.async.commit_group;" ::: "memory");
            asm volatile("cp.async.wait_group 1;" ::: "memory");
        } else {
            asm volatile("cp.async.wait_group 0;" ::: "memory");
        }
        __syncthreads();
        uint32_t base = cx.sb + buf * 40960;
#pragma unroll
        for (int k16 = 0; k16 < 2; k16++){
            uint32_t ac = (uint32_t)k16 * 32 + aColOff;
            uint32_t bc = (uint32_t)k16 * 32 + bColOff;
            uint32_t ah[4][4], al[4][4], bh[2][4], bl[2][4];
#pragma unroll
            for (int mi = 0; mi < 4; mi++){
                uint32_t ad = base + (uint32_t)(wm * 64 + mi * 16) * 80 + aRowOff + ac;
                ldmx4(ah[mi], ad);
                ldmx4(al[mi], ad + 10240);
            }
#pragma unroll
            for (int ng = 0; ng < 2; ng++){
                uint32_t bd = base + 20480 + (uint32_t)(wn * 32 + ng * 16) * 80 + bRowOff + bc;
                ldmx4(bh[ng], bd);
                ldmx4(bl[ng], bd + 10240);
            }
#pragma unroll
            for (int mi = 0; mi < 4; mi++){
#pragma unroll
                for (int ni = 0; ni < 4; ni++){
                    const uint32_t* bhp = &bh[ni >> 1][(ni & 1) * 2];
                    const uint32_t* blp = &bl[ni >> 1][(ni & 1) * 2];
                    mma_bf16(acc[mi][ni], ah[mi], bhp);
                    mma_bf16(acc[mi][ni], ah[mi], blp);
                    mma_bf16(acc[mi][ni], al[mi], bhp);
                }
            }
        }
        __syncthreads();
    }

    int tb = n0 / HW;
    int hw0 = n0 - tb * HW;
#pragma unroll
    for (int mi = 0; mi < 4; mi++){
        int mrow = m0 + wm * 64 + mi * 16 + (lane >> 2);
#pragma unroll
        for (int ni = 0; ni < 4; ni++){
            int col = hw0 + wn * 32 + ni * 8 + (lane & 3) * 2;
            float2 v0 = make_float2(acc[mi][ni][0], acc[mi][ni][1]);
            float2 v1 = make_float2(acc[mi][ni][2], acc[mi][ni][3]);
            *(float2*)&out[((size_t)(tb * M + mrow)) * HW + col]     = v0;
            *(float2*)&out[((size_t)(tb * M + mrow + 8)) * HW + col] = v1;
        }
    }
}

// ---------------- fp32 GEMM (qkv / classifier) ----------------
__global__ __launch_bounds__(256) void gemm_conv_kernel(
    const float* __restrict__ Wt, const float* __restrict__ p0,
    int M, int Cin, const float* __restrict__ bias, float* __restrict__ out)
{
    __shared__ float As[16][128];
    __shared__ float Bs[16][128];
    const int tid = threadIdx.x;
    const int tx = tid & 15, ty = tid >> 4;
    const int m0 = blockIdx.y * 128;
    const int n0 = blockIdx.x * 128;
    float acc[8][8];
#pragma unroll
    for (int i = 0; i < 8; i++)
#pragma unroll
        for (int j = 0; j < 8; j++) acc[i][j] = 0.f;
    const int nl = tid & 127;
    const int nglob = n0 + nl;
    const int bb = nglob / HW;
    const int hw = nglob - bb * HW;
    const int kbB = (tid >> 7) * 8;
    const int ml = tid >> 1;
    const int kbA = (tid & 1) * 8;
    for (int k0 = 0; k0 < Cin; k0 += 16){
        int m = m0 + ml;
        const float* wp = Wt + (size_t)m * Cin + (k0 + kbA);
#pragma unroll
        for (int i = 0; i < 8; i++)
            As[kbA + i][ml] = (m < M) ? wp[i] : 0.f;
#pragma unroll
        for (int i = 0; i < 8; i++)
            Bs[kbB + i][nl] = p0[((size_t)(bb * Cin + k0 + kbB + i)) * HW + hw];
        __syncthreads();
#pragma unroll
        for (int kk = 0; kk < 16; kk++){
            float a[8], bq[8];
#pragma unroll
            for (int i = 0; i < 8; i++) a[i]  = As[kk][ty + 16 * i];
#pragma unroll
            for (int j = 0; j < 8; j++) bq[j] = Bs[kk][tx + 16 * j];
#pragma unroll
            for (int i = 0; i < 8; i++)
#pragma unroll
                for (int j = 0; j < 8; j++)
                    acc[i][j] = fmaf(a[i], bq[j], acc[i][j]);
        }
        __syncthreads();
    }
#pragma unroll
    for (int i = 0; i < 8; i++){
        int m = m0 + ty + 16 * i;
        if (m >= M) continue;
        float bval = bias ? bias[m] : 0.f;
#pragma unroll
        for (int j = 0; j < 8; j++){
            int n = n0 + tx + 16 * j;
            int b = n / HW;
            int hw2 = n - b * HW;
            out[((size_t)(b * M + m)) * HW + hw2] = acc[i][j] + bval;
        }
    }
}

// ---------------- BatchNorm ----------------
__global__ void bn_stats_kernel(const float* __restrict__ x,
                                const float* __restrict__ g,
                                const float* __restrict__ bta,
                                float* __restrict__ stats, int C)
{
    int c = blockIdx.x, tid = threadIdx.x;
    float s = 0.f, sq = 0.f;
    for (int i = tid; i < NB * HW; i += 256){
        int bb = i / HW;
        float v = x[((size_t)(bb * C + c)) * HW + (i - bb * HW)];
        s += v; sq += v * v;
    }
    __shared__ float sh1[256], sh2[256];
    sh1[tid] = s; sh2[tid] = sq;
    __syncthreads();
    for (int st = 128; st; st >>= 1){
        if (tid < st){ sh1[tid] += sh1[tid + st]; sh2[tid] += sh2[tid + st]; }
        __syncthreads();
    }
    if (tid == 0){
        float n = (float)(NB * HW);
        float m = sh1[0] / n;
        float var = sh2[0] / n - m * m;
        float sc = g[c] * rsqrtf(var + 1e-5f);
        stats[2 * c] = sc;
        stats[2 * c + 1] = bta[c] - m * sc;
    }
}

__global__ void bn_apply_kernel(const float* __restrict__ x,
                                const float* __restrict__ stats,
                                float* __restrict__ y, int C, int total)
{
    int i = blockIdx.x * 256 + threadIdx.x;
    if (i < total){
        int c = (i / HW) % C;
        y[i] = fmaxf(fmaf(x[i], stats[2 * c], stats[2 * c + 1]), 0.f);
    }
}

// ---------------- criss-cross attention (tiled) ----------------
__global__ void cc_logits_col_kernel(const float* __restrict__ q,
                                     const float* __restrict__ k,
                                     float* __restrict__ att)
{
    int w = blockIdx.x, b = blockIdx.y, tid = threadIdx.x;
    __shared__ float qs[32][48], ks[32][48];
    for (int i = tid; i < 32 * 48; i += 256){
        int c = i / 48, h = i - (i / 48) * 48;
        qs[c][h] = q[((size_t)((b * 32 + c) * 48 + h)) * 48 + w];
        ks[c][h] = k[((size_t)((b * 32 + c) * 48 + h)) * 48 + w];
    }
    __syncthreads();
    for (int i = tid; i < 48 * 48; i += 256){
        int h = i / 48, g = i - (i / 48) * 48;
        float s;
        if (g == h) s = NEG_INF;
        else {
            s = 0.f;
#pragma unroll
            for (int c = 0; c < 32; c++) s += qs[c][h] * ks[c][g];
        }
        att[((size_t)((b * 48 + h) * 48 + w)) * 96 + g] = s;
    }
}

__global__ void cc_logits_row_kernel(const float* __restrict__ q,
                                     const float* __restrict__ k,
                                     float* __restrict__ att)
{
    int h = blockIdx.x, b = blockIdx.y, tid = threadIdx.x;
    __shared__ float qs[32][48], ks[32][48];
    for (int i = tid; i < 32 * 48; i += 256){
        int c = i / 48, w = i - (i / 48) * 48;
        qs[c][w] = q[((size_t)((b * 32 + c) * 48 + h)) * 48 + w];
        ks[c][w] = k[((size_t)((b * 32 + c) * 48 + h)) * 48 + w];
    }
    __syncthreads();
    for (int i = tid; i < 48 * 48; i += 256){
        int w = i / 48, v2 = i - (i / 48) * 48;
        float s = 0.f;
#pragma unroll
        for (int c = 0; c < 32; c++) s += qs[c][w] * ks[c][v2];
        att[((size_t)((b * 48 + h) * 48 + w)) * 96 + 48 + v2] = s;
    }
}

__global__ void cc_softmax_kernel(float* __restrict__ att)
{
    int row  = blockIdx.x * 8 + (threadIdx.x >> 5);
    int lane = threadIdx.x & 31;
    float* p = att + (size_t)row * 96;
    float v0 = p[lane], v1 = p[lane + 32], v2 = p[lane + 64];
    float mx = fmaxf(v0, fmaxf(v1, v2));
#pragma unroll
    for (int off = 16; off; off >>= 1) mx = fmaxf(mx, __shfl_xor_sync(0xffffffff, mx, off));
    float e0 = expf(v0 - mx), e1 = expf(v1 - mx), e2 = expf(v2 - mx);
    float s = e0 + e1 + e2;
#pragma unroll
    for (int off = 16; off; off >>= 1) s += __shfl_xor_sync(0xffffffff, s, off);
    float inv = 1.f / s;
    p[lane] = e0 * inv; p[lane + 32] = e1 * inv; p[lane + 64] = e2 * inv;
}

#define CC_SMEM ((256*48 + 48*48) * 4)

__global__ void cc_out_col_kernel(const float* __restrict__ v,
                                  const float* __restrict__ att,
                                  const float* __restrict__ xin,
                                  const float* __restrict__ gamma,
                                  float* __restrict__ out)
{
    extern __shared__ float cs[];
    float* vs = cs; float* as = cs + 256 * 48;
    int w = blockIdx.x, b = blockIdx.y, tid = threadIdx.x;
    for (int i = tid; i < 256 * 48; i += 256){
        int c = i / 48, g = i - (i / 48) * 48;
        vs[i] = v[((size_t)((b * 256 + c) * 48 + g)) * 48 + w];
    }
    for (int i = tid; i < 48 * 48; i += 256){
        int h = i / 48, g = i - (i / 48) * 48;
        as[i] = att[((size_t)((b * 48 + h) * 48 + w)) * 96 + g];
    }
    __syncthreads();
    float gm = gamma[0];
    for (int i = tid; i < 256 * 48; i += 256){
        int c = i / 48, h = i - (i / 48) * 48;
        float s = 0.f;
#pragma unroll
        for (int g = 0; g < 48; g++) s += vs[c * 48 + g] * as[h * 48 + g];
        size_t o = ((size_t)((b * 256 + c) * 48 + h)) * 48 + w;
        out[o] = xin[o] + gm * s;
    }
}

__global__ void cc_out_row_kernel(const float* __restrict__ v,
                                  const float* __restrict__ att,
                                  const float* __restrict__ gamma,
                                  float* __restrict__ out)
{
    extern __shared__ float cs[];
    float* vs = cs; float* as = cs + 256 * 48;
    int h = blockIdx.x, b = blockIdx.y, tid = threadIdx.x;
    for (int i = tid; i < 256 * 48; i += 256){
        vs[i] = v[((size_t)(b * 256 + i / 48) * 48 + h) * 48 + (i % 48)];
    }
    for (int i = tid; i < 48 * 48; i += 256){
        int w2 = i / 48, v2 = i - (i / 48) * 48;
        as[i] = att[((size_t)((b * 48 + h) * 48 + w2)) * 96 + 48 + v2];
    }
    __syncthreads();
    float gm = gamma[0];
    for (int i = tid; i < 256 * 48; i += 256){
        int c = i / 48, w2 = i - (i / 48) * 48;
        float s = 0.f;
#pragma unroll
        for (int v2 = 0; v2 < 48; v2++) s += vs[c * 48 + v2] * as[w2 * 48 + v2];
        size_t o = ((size_t)((b * 256 + c) * 48 + h)) * 48 + w2;
        out[o] += gm * s;
    }
}

// ---------------- grid attention ----------------
__global__ void gram_kernel(const float* __restrict__ q,
                            const float* __restrict__ k,
                            float* __restrict__ S)
{
    int b1 = blockIdx.x >> 4, b2 = blockIdx.x & 15;
    const float* qp = q + (size_t)b1 * (C8 * HW);
    const float* kp = k + (size_t)b2 * (C8 * HW);
    int tid = threadIdx.x;
    float s = 0.f;
    for (int i = tid; i < C8 * HW; i += 256) s += qp[i] * kp[i];
    __shared__ float sh[256];
    sh[tid] = s;
    __syncthreads();
    for (int st = 128; st; st >>= 1){
        if (tid < st) sh[tid] += sh[tid + st];
        __syncthreads();
    }
    if (tid == 0) S[blockIdx.x] = sh[0];
}

__global__ void myw_kernel(const float* __restrict__ S, float* __restrict__ Wm)
{
    int b1 = threadIdx.x;
    if (b1 < 16){
        int gh = b1 >> 2, gw = b1 & 3;
        float l[8];
        for (int j = 0; j < 4; j++){
            int b2 = j * 4 + gw;
            l[j] = (j == gh) ? NEG_INF : S[b1 * 16 + b2];
        }
        for (int j = 0; j < 4; j++) l[4 + j] = S[b1 * 16 + gh * 4 + j];
        float mx = NEG_INF;
        for (int j = 0; j < 8; j++) mx = fmaxf(mx, l[j]);
        float sm = 0.f;
        for (int j = 0; j < 8; j++){ l[j] = expf(l[j] - mx); sm += l[j]; }
        float inv = 1.f / sm;
        float w[16];
        for (int i = 0; i < 16; i++) w[i] = 0.f;
        for (int j = 0; j < 4; j++) w[j * 4 + gw] += l[j] * inv;
        for (int j = 0; j < 4; j++) w[gh * 4 + j] += l[4 + j] * inv;
        for (int i = 0; i < 16; i++) Wm[b1 * 16 + i] = w[i];
    }
}

__global__ void my_combine_kernel(const float* __restrict__ v,
                                  const float* __restrict__ Wm,
                                  const float* __restrict__ xin,
                                  const float* __restrict__ gamma,
                                  float* __restrict__ out)
{
    __shared__ float ws[256];
    if (threadIdx.x < 256) ws[threadIdx.x] = Wm[threadIdx.x];
    __syncthreads();
    const int PB = CMID * HW;
    int n = blockIdx.x * 256 + threadIdx.x;
    if (n < PB){
        float vv[16];
#pragma unroll
        for (int b = 0; b < 16; b++) vv[b] = v[(size_t)b * PB + n];
        float gm = gamma[0];
#pragma unroll
        for (int b1 = 0; b1 < 16; b1++){
            float o = 0.f;
#pragma unroll
            for (int b2 = 0; b2 < 16; b2++) o += ws[b1 * 16 + b2] * vv[b2];
            out[(size_t)b1 * PB + n] = gm * o + xin[(size_t)b1 * PB + n];
        }
    }
}

// ---------------- host ----------------
extern "C" void kernel_launch(void* const* d_in, const int* in_sizes, int n_in,
                              void* d_out, int out_size)
{
    const float* x      = (const float*)d_in[0];
    const float* w_a    = (const float*)d_in[1];
    const float* g_a    = (const float*)d_in[2];
    const float* b_a    = (const float*)d_in[3];
    const float* ccq_w  = (const float*)d_in[4];
    const float* ccq_b  = (const float*)d_in[5];
    const float* cck_w  = (const float*)d_in[6];
    const float* cck_b  = (const float*)d_in[7];
    const float* ccv_w  = (const float*)d_in[8];
    const float* ccv_b  = (const float*)d_in[9];
    const float* cc_gm  = (const float*)d_in[10];
    const float* w_b    = (const float*)d_in[11];
    const float* g_b    = (const float*)d_in[12];
    const float* b_b    = (const float*)d_in[13];
    const float* w_m1   = (const float*)d_in[14];
    const float* g_m1   = (const float*)d_in[15];
    const float* b_m1   = (const float*)d_in[16];
    const float* myq_w  = (const float*)d_in[17];
    const float* myq_b  = (const float*)d_in[18];
    const float* myk_w  = (const float*)d_in[19];
    const float* myk_b  = (const float*)d_in[20];
    const float* myv_w  = (const float*)d_in[21];
    const float* myv_b  = (const float*)d_in[22];
    const float* my_gm  = (const float*)d_in[23];
    const float* w_m2   = (const float*)d_in[24];
    const float* g_m2   = (const float*)d_in[25];
    const float* b_m2   = (const float*)d_in[26];
    const float* w_c    = (const float*)d_in[27];
    const float* g_c    = (const float*)d_in[28];
    const float* b_c    = (const float*)d_in[29];
    const float* w_cls  = (const float*)d_in[30];
    const float* b_cls  = (const float*)d_in[31];

    cudaFuncSetAttribute(mma_conv_kernel, cudaFuncAttributeMaxDynamicSharedMemorySize, MC_SMEM);
    cudaFuncSetAttribute(cc_out_col_kernel, cudaFuncAttributeMaxDynamicSharedMemorySize, CC_SMEM);
    cudaFuncSetAttribute(cc_out_row_kernel, cudaFuncAttributeMaxDynamicSharedMemorySize, CC_SMEM);

    float *pt0, *pcc, *pmy, *pt1, *pq, *pk, *pv, *ph, *pst, *pS, *pWm, *patt;
    cudaGetSymbolAddress((void**)&pt0, g_t0);
    cudaGetSymbolAddress((void**)&pcc, g_cc);
    cudaGetSymbolAddress((void**)&pmy, g_my);
    cudaGetSymbolAddress((void**)&pt1, g_t1);
    cudaGetSymbolAddress((void**)&pq,  g_q);
    cudaGetSymbolAddress((void**)&pk,  g_k);
    cudaGetSymbolAddress((void**)&pv,  g_v);
    cudaGetSymbolAddress((void**)&ph,  g_h);
    cudaGetSymbolAddress((void**)&pst, g_stats);
    cudaGetSymbolAddress((void**)&pS,  g_S);
    cudaGetSymbolAddress((void**)&pWm, g_Wm);
    cudaGetSymbolAddress((void**)&patt, g_att);

    __nv_bfloat16 *XCh,*XCl,*ACTh,*ACTl;
    __nv_bfloat16 *WAh,*WAl,*WM1h,*WM1l,*WBh,*WBl,*WM2h,*WM2l,*WCh,*WCl;
    cudaGetSymbolAddress((void**)&XCh, g_XCh);   cudaGetSymbolAddress((void**)&XCl, g_XCl);
    cudaGetSymbolAddress((void**)&ACTh, g_ACTh); cudaGetSymbolAddress((void**)&ACTl, g_ACTl);
    cudaGetSymbolAddress((void**)&WAh, g_WAh);   cudaGetSymbolAddress((void**)&WAl, g_WAl);
    cudaGetSymbolAddress((void**)&WM1h, g_WM1h); cudaGetSymbolAddress((void**)&WM1l, g_WM1l);
    cudaGetSymbolAddress((void**)&WBh, g_WBh);   cudaGetSymbolAddress((void**)&WBl, g_WBl);
    cudaGetSymbolAddress((void**)&WM2h, g_WM2h); cudaGetSymbolAddress((void**)&WM2l, g_WM2l);
    cudaGetSymbolAddress((void**)&WCh, g_WCh);   cudaGetSymbolAddress((void**)&WCl, g_WCl);

    const dim3 blk(256);
    const dim3 tr_blk(32, 8);
    const int NT = NTOT / 128;
    const int TOT_MID = NB*CMID*HW;

    // weight prep
    wprep_kernel<<<(256*9216 + 255)/256, blk>>>(w_a,  WAh,  WAl,  256, 1024, 9);
    wprep_kernel<<<(256*9216 + 255)/256, blk>>>(w_m1, WM1h, WM1l, 256, 1024, 9);
    wprep_kernel<<<(256*2304 + 255)/256, blk>>>(w_b,  WBh,  WBl,  256, 256, 9);
    wprep_kernel<<<(256*2304 + 255)/256, blk>>>(w_m2, WM2h, WM2l, 256, 256, 9);
    wprep_kernel<<<(512*13824 + 255)/256, blk>>>(w_c, WCh,  WCl,  512, 1536, 9);

    // x -> XC[0:1024]
    to_nhwc_kernel<<<dim3(HW/32, 1024/32, NB), tr_blk>>>(x, XCh, XCl, 1024, 1536, 0);

    // conv_a, conv_m1
    mma_conv_kernel<<<dim3(NT, 2), blk, MC_SMEM>>>(WAh, WAl, XCh, XCl, 256, 1024, 9, 1536, 0, pt0);
    bn_stats_kernel<<<CMID, blk>>>(pt0, g_a, b_a, pst, CMID);
    bn_apply_kernel<<<(TOT_MID + 255)/256, blk>>>(pt0, pst, pcc, CMID, TOT_MID);

    mma_conv_kernel<<<dim3(NT, 2), blk, MC_SMEM>>>(WM1h, WM1l, XCh, XCl, 256, 1024, 9, 1536, 0, pt0);
    bn_stats_kernel<<<CMID, blk>>>(pt0, g_m1, b_m1, pst, CMID);
    bn_apply_kernel<<<(TOT_MID + 255)/256, blk>>>(pt0, pst, pmy, CMID, TOT_MID);

    // cc attention x2 (tiled)
    {
        float* ca = pcc; float* cb = pt1;
        for (int it = 0; it < 2; it++){
            gemm_conv_kernel<<<dim3(NT, 1), blk>>>(ccq_w, ca, C8,   CMID, ccq_b, pq);
            gemm_conv_kernel<<<dim3(NT, 1), blk>>>(cck_w, ca, C8,   CMID, cck_b, pk);
            gemm_conv_kernel<<<dim3(NT, 2), blk>>>(ccv_w, ca, CMID, CMID, ccv_b, pv);
            cc_logits_col_kernel<<<dim3(WW, NB), blk>>>(pq, pk, patt);
            cc_logits_row_kernel<<<dim3(HH, NB), blk>>>(pq, pk, patt);
            cc_softmax_kernel<<<NTOT/8, blk>>>(patt);
            cc_out_col_kernel<<<dim3(WW, NB), blk, CC_SMEM>>>(pv, patt, ca, cc_gm, cb);
            cc_out_row_kernel<<<dim3(HH, NB), blk, CC_SMEM>>>(pv, patt, cc_gm, cb);
            float* tmp = ca; ca = cb; cb = tmp;
        }
    }

    // my attention x2
    {
        float* ma = pmy; float* mb = pt1 == pmy ? pt1 : pt1;  // keep simple
        mb = pt1;
        // note: pt1 was used by cc ping-pong; final cc result is in pcc (even swaps)
        for (int it = 0; it < 2; it++){
            gemm_conv_kernel<<<dim3(NT, 1), blk>>>(myq_w, ma, C8,   CMID, myq_b, pq);
            gemm_conv_kernel<<<dim3(NT, 1), blk>>>(myk_w, ma, C8,   CMID, myk_b, pk);
            gemm_conv_kernel<<<dim3(NT, 2), blk>>>(myv_w, ma, CMID, CMID, myv_b, pv);
            gram_kernel<<<256, blk>>>(pq, pk, pS);
            myw_kernel<<<1, 32>>>(pS, pWm);
            my_combine_kernel<<<(CMID*HW + 255)/256, blk>>>(pv, pWm, ma, my_gm, mb);
            float* tmp = ma; ma = mb; mb = tmp;
        }
    }

    // conv_b: input pcc -> BN -> XC@1024 (fused)
    to_nhwc_kernel<<<dim3(HW/32, 256/32, NB), tr_blk>>>(pcc, ACTh, ACTl, 256, 256, 0);
    mma_conv_kernel<<<dim3(NT, 2), blk, MC_SMEM>>>(WBh, WBl, ACTh, ACTl, 256, 256, 9, 256, 0, pt0);
    bn_stats_kernel<<<CMID, blk>>>(pt0, g_b, b_b, pst, CMID);
    bn_to_nhwc_kernel<<<dim3(HW/32, 256/32, NB), tr_blk>>>(pt0, pst, XCh, XCl, 256, 1536, 1024);

    // conv_m2: input pmy -> BN -> XC@1280 (fused)
    to_nhwc_kernel<<<dim3(HW/32, 256/32, NB), tr_blk>>>(pmy, ACTh, ACTl, 256, 256, 0);
    mma_conv_kernel<<<dim3(NT, 2), blk, MC_SMEM>>>(WM2h, WM2l, ACTh, ACTl, 256, 256, 9, 256, 0, pt0);
    bn_stats_kernel<<<CMID, blk>>>(pt0, g_m2, b_m2, pst, CMID);
    bn_to_nhwc_kernel<<<dim3(HW/32, 256/32, NB), tr_blk>>>(pt0, pst, XCh, XCl, 256, 1536, 1280);

    // conv_c + BN
    mma_conv_kernel<<<dim3(NT, 4), blk, MC_SMEM>>>(WCh, WCl, XCh, XCl, 512, 1536, 9, 1536, 0, ph);
    bn_stats_kernel<<<OCH, blk>>>(ph, g_c, b_c, pst, OCH);
    bn_apply_kernel<<<(NB*OCH*HW + 255)/256, blk>>>(ph, pst, ph, OCH, NB*OCH*HW);

    // classifier
    gemm_conv_kernel<<<dim3(NT, 1), blk>>>(w_cls, ph, NCLS, OCH, b_cls, (float*)d_out);
}